// round 12
// baseline (speedup 1.0000x reference)
#include <cuda_runtime.h>
#include <cuda_fp16.h>
#include <math.h>

#define NN 8192
#define TT 60
#define HH 64

__device__ float g_xt[(size_t)TT*NN*8];
__device__ float g_hidden[NN*HH];
__device__ float g_s1[NN];
__device__ float g_s2[NN];
__device__ unsigned long long g_keys[NN];
__device__ float g_s1s[NN];
__device__ int   g_perm[NN];
__device__ double g_e1[NN];
__device__ double g_e01[NN];
__device__ double g_prefP[(NN+1)*HH];
__device__ double g_prefQ[(NN+1)*HH];
__device__ double g_prefE[(NN+1)*2];

__device__ __forceinline__ float sig_f(float x){ return 1.f/(1.f+__expf(-x)); }
__device__ __forceinline__ float tanh_f(float x){ return 1.f-2.f/(__expf(2.f*x)+1.f); }

__device__ __forceinline__ unsigned pk2h(float lo, float hi){
    unsigned r;
    asm("{.reg .b16 l,h;\n cvt.rn.f16.f32 l, %1;\n cvt.rn.f16.f32 h, %2;\n mov.b32 %0, {l,h};}"
        : "=r"(r) : "f"(lo), "f"(hi));
    return r;
}
__device__ __forceinline__ float hfr(float v){
    float o;
    asm("{.reg .b16 t;\n cvt.rn.f16.f32 t, %1;\n cvt.f32.f16 %0, t;}" : "=f"(o) : "f"(v));
    return o;
}
__device__ __forceinline__ unsigned short h16(float v){
    unsigned short s;
    asm("{.reg .b16 t;\n cvt.rn.f16.f32 t, %1;\n mov.b16 %0, t;}" : "=h"(s) : "f"(v));
    return s;
}
__device__ __forceinline__ float2 uhf2(unsigned u){
    float2 f;
    asm("{.reg .b16 l,h;\n mov.b32 {l,h}, %2;\n cvt.f32.f16 %0, l;\n cvt.f32.f16 %1, h;}"
        : "=f"(f.x), "=f"(f.y) : "r"(u));
    return f;
}

#define MMA16(C, A, B0, B1) \
    asm("mma.sync.aligned.m16n8k16.row.col.f32.f16.f16.f32 " \
        "{%0,%1,%2,%3},{%4,%5,%6,%7},{%8,%9},{%0,%1,%2,%3};" \
        : "+f"(C[0]),"+f"(C[1]),"+f"(C[2]),"+f"(C[3]) \
        : "r"((A)[0]),"r"((A)[1]),"r"((A)[2]),"r"((A)[3]),"r"(B0),"r"(B1))

#define MMA8(C, A0, A1, B0) \
    asm("mma.sync.aligned.m16n8k8.row.col.f32.f16.f16.f32 " \
        "{%0,%1,%2,%3},{%4,%5},{%6},{%0,%1,%2,%3};" \
        : "+f"(C[0]),"+f"(C[1]),"+f"(C[2]),"+f"(C[3]) \
        : "r"(A0),"r"(A1),"r"(B0))

#define LDSM4(Q, ADDR) \
    asm volatile("ldmatrix.sync.aligned.m8n8.x4.shared.b16 {%0,%1,%2,%3},[%4];" \
        : "=r"(Q.x),"=r"(Q.y),"=r"(Q.z),"=r"(Q.w) : "r"(ADDR))

#define LDSM4A(A, ADDR) \
    asm volatile("ldmatrix.sync.aligned.m8n8.x4.shared.b16 {%0,%1,%2,%3},[%4];" \
        : "=r"((A)[0]),"=r"((A)[1]),"=r"((A)[2]),"=r"((A)[3]) : "r"(ADDR) : "memory")

#define STS32(ADDR, V) \
    asm volatile("st.shared.u32 [%0], %1;" :: "r"(ADDR), "r"(V) : "memory")

// smem byte offsets (S0 and S1 both double-buffered: 2 x 9216 each region)
#define XWHI 0
#define W0HI 3072
#define WI1HI 30720
#define WH1HI 58368
#define BIASO 86016
#define S0HI 88064
#define S0LO 106496
#define S1HI 124928
#define S1LO 143360
#define SMEM_GRU 161792

__device__ __forceinline__ unsigned smem_u32(const void* p){
    unsigned a; asm("{ .reg .u64 t; cvta.to.shared.u64 t, %1; cvt.u32.u64 %0, t; }" : "=r"(a) : "l"(p));
    return a;
}

#define GATE_EPI2(Cr,Cz,Ci,Chn, BOFF, n0_, AHI, ALO, i0_, SH_, SL_) do{ \
    float2 _br = *(const float2*)(sbias + (BOFF) + (n0_) + 2*c); \
    float2 _bz = *(const float2*)(sbias + (BOFF) + 64 + (n0_) + 2*c); \
    float2 _bi = *(const float2*)(sbias + (BOFF) + 128 + (n0_) + 2*c); \
    float2 _bh = *(const float2*)(sbias + (BOFF) + 192 + (n0_) + 2*c); \
    float2 _p0 = uhf2((AHI)[i0_]),   _q0 = uhf2((ALO)[i0_]); \
    float2 _p1 = uhf2((AHI)[i0_+1]), _q1 = uhf2((ALO)[i0_+1]); \
    float _hp0=_p0.x+_q0.x, _hp1=_p0.y+_q0.y, _hp2=_p1.x+_q1.x, _hp3=_p1.y+_q1.y; \
    float _r0=sig_f(Cr[0]+_br.x), _r1=sig_f(Cr[1]+_br.y), _r2=sig_f(Cr[2]+_br.x), _r3=sig_f(Cr[3]+_br.y); \
    float _z0=sig_f(Cz[0]+_bz.x), _z1=sig_f(Cz[1]+_bz.y), _z2=sig_f(Cz[2]+_bz.x), _z3=sig_f(Cz[3]+_bz.y); \
    float _n0=tanh_f(Ci[0]+_bi.x+_r0*(Chn[0]+_bh.x)); \
    float _n1=tanh_f(Ci[1]+_bi.y+_r1*(Chn[1]+_bh.y)); \
    float _n2=tanh_f(Ci[2]+_bi.x+_r2*(Chn[2]+_bh.x)); \
    float _n3=tanh_f(Ci[3]+_bi.y+_r3*(Chn[3]+_bh.y)); \
    float _h0=_n0+_z0*(_hp0-_n0), _h1=_n1+_z1*(_hp1-_n1); \
    float _h2=_n2+_z2*(_hp2-_n2), _h3=_n3+_z3*(_hp3-_n3); \
    STS32((SH_) + (n0_)*2,        pk2h(_h0,_h1)); \
    STS32((SH_) + (n0_)*2 + 1152, pk2h(_h2,_h3)); \
    STS32((SL_) + (n0_)*2,        pk2h(_h0-hfr(_h0), _h1-hfr(_h1))); \
    STS32((SL_) + (n0_)*2 + 1152, pk2h(_h2-hfr(_h2), _h3-hfr(_h3))); \
}while(0)

#define L0_TILE(t8, XH0,XH1,XL0,XL1) do{ \
    const int n0 = (t8)*8; \
    float Cr[4]={0,0,0,0}, Cz[4]={0,0,0,0}, Ci[4]={0,0,0,0}, Chn[4]={0,0,0,0}; \
    uint4 qx; LDSM4(qx, a_x + n0*16); \
    MMA8(Cr,XH0,XH1,qx.x); MMA8(Cz,XH0,XH1,qx.y); MMA8(Ci,XH0,XH1,qx.z); \
    MMA8(Cr,XL0,XL1,qx.x); MMA8(Cz,XL0,XL1,qx.y); MMA8(Ci,XL0,XL1,qx.z); \
    _Pragma("unroll") \
    for (int kp=0; kp<2; kp++){ \
        uint4 qr, qz, qn; \
        LDSM4(qr, a_w0 + n0*144 + kp*64); \
        LDSM4(qz, a_w0 + 9216 + n0*144 + kp*64); \
        LDSM4(qn, a_w0 + 18432 + n0*144 + kp*64); \
        const int k0 = 2*kp; \
        MMA16(Cr, a0h[k0], qr.x, qr.y); MMA16(Cz, a0h[k0], qz.x, qz.y); MMA16(Chn, a0h[k0], qn.x, qn.y); \
        MMA16(Cr, a0l[k0], qr.x, qr.y); MMA16(Cz, a0l[k0], qz.x, qz.y); MMA16(Chn, a0l[k0], qn.x, qn.y); \
        MMA16(Cr, a0h[k0+1], qr.z, qr.w); MMA16(Cz, a0h[k0+1], qz.z, qz.w); MMA16(Chn, a0h[k0+1], qn.z, qn.w); \
        MMA16(Cr, a0l[k0+1], qr.z, qr.w); MMA16(Cz, a0l[k0+1], qz.z, qz.w); MMA16(Chn, a0l[k0+1], qn.z, qn.w); \
    } \
    const int kt0 = (t8)>>1, i0 = ((t8)&1)*2; \
    GATE_EPI2(Cr,Cz,Ci,Chn, 0, n0, a0h[kt0], a0l[kt0], i0, st0h, st0l); \
}while(0)

#define L1_TILE(t8) do{ \
    const int n0 = (t8)*8; \
    float Cri[4]={0,0,0,0}, Crh[4]={0,0,0,0}, Czi[4]={0,0,0,0}, Czh[4]={0,0,0,0}; \
    float Cii[4]={0,0,0,0}, Chn[4]={0,0,0,0}; \
    _Pragma("unroll") \
    for (int kp=0; kp<2; kp++){ \
        uint4 q0,q1,q2,q3,q4,q5; \
        LDSM4(q0, a_i1 + n0*144 + kp*64); \
        LDSM4(q1, a_h1 + n0*144 + kp*64); \
        LDSM4(q2, a_i1 + 9216 + n0*144 + kp*64); \
        LDSM4(q3, a_h1 + 9216 + n0*144 + kp*64); \
        LDSM4(q4, a_i1 + 18432 + n0*144 + kp*64); \
        LDSM4(q5, a_h1 + 18432 + n0*144 + kp*64); \
        const int k0 = 2*kp; \
        MMA16(Cri, yh[k0], q0.x, q0.y); MMA16(Crh, a1h[k0], q1.x, q1.y); \
        MMA16(Czi, yh[k0], q2.x, q2.y); MMA16(Czh, a1h[k0], q3.x, q3.y); \
        MMA16(Cii, yh[k0], q4.x, q4.y); MMA16(Chn, a1h[k0], q5.x, q5.y); \
        MMA16(Cri, yl[k0], q0.x, q0.y); MMA16(Crh, a1l[k0], q1.x, q1.y); \
        MMA16(Czi, yl[k0], q2.x, q2.y); MMA16(Czh, a1l[k0], q3.x, q3.y); \
        MMA16(Cii, yl[k0], q4.x, q4.y); MMA16(Chn, a1l[k0], q5.x, q5.y); \
        MMA16(Cri, yh[k0+1], q0.z, q0.w); MMA16(Crh, a1h[k0+1], q1.z, q1.w); \
        MMA16(Czi, yh[k0+1], q2.z, q2.w); MMA16(Czh, a1h[k0+1], q3.z, q3.w); \
        MMA16(Cii, yh[k0+1], q4.z, q4.w); MMA16(Chn, a1h[k0+1], q5.z, q5.w); \
        MMA16(Cri, yl[k0+1], q0.z, q0.w); MMA16(Crh, a1l[k0+1], q1.z, q1.w); \
        MMA16(Czi, yl[k0+1], q2.z, q2.w); MMA16(Czh, a1l[k0+1], q3.z, q3.w); \
        MMA16(Cii, yl[k0+1], q4.z, q4.w); MMA16(Chn, a1l[k0+1], q5.z, q5.w); \
    } \
    float Cr[4], Cz[4]; \
    _Pragma("unroll") \
    for (int i=0;i<4;i++){ Cr[i]=Cri[i]+Crh[i]; Cz[i]=Czi[i]+Czh[i]; } \
    const int kt0 = (t8)>>1, i0 = ((t8)&1)*2; \
    GATE_EPI2(Cr,Cz,Cii,Chn, 256, n0, a1h[kt0], a1l[kt0], i0, st1h, st1l); \
}while(0)

__global__ __launch_bounds__(256) void transpose_kernel(const float* __restrict__ x){
    __shared__ float sx[32*360];
    int nb = blockIdx.x*32, tid = threadIdx.x;
    for (int idx=tid; idx<32*360; idx+=256) sx[idx] = x[(size_t)nb*360 + idx];
    __syncthreads();
    int n = tid>>3, d = tid&7;
    float* op = g_xt + ((size_t)(nb+n))*8 + d;
    #pragma unroll 4
    for (int t=0; t<TT; t++)
        op[(size_t)t*NN*8] = (d<6) ? sx[n*360 + d*60 + t] : 0.f;
}

__global__ __launch_bounds__(1024,1) void gru_kernel(
    const float* __restrict__ Wih0, const float* __restrict__ Whh0,
    const float* __restrict__ bih0, const float* __restrict__ bhh0,
    const float* __restrict__ Wih1, const float* __restrict__ Whh1,
    const float* __restrict__ bih1, const float* __restrict__ bhh1)
{
    extern __shared__ char sm[];
    const int tid = threadIdx.x;
    unsigned short* xw = (unsigned short*)(sm + XWHI);
    for (int i=tid; i<1536; i+=1024) xw[i]=0;
    for (int i=tid; i<1152; i+=1024){
        int n = i/6, d = i - n*6;
        xw[n*8+d] = h16(Wih0[i]);
    }
    {
        unsigned short* w0 = (unsigned short*)(sm + W0HI);
        unsigned short* i1 = (unsigned short*)(sm + WI1HI);
        unsigned short* h1 = (unsigned short*)(sm + WH1HI);
        for (int i=tid; i<12288; i+=1024){
            int n = i>>6, k = i&63, o = n*72+k;
            w0[o] = h16(Whh0[i]);
            i1[o] = h16(Wih1[i]);
            h1[o] = h16(Whh1[i]);
        }
    }
    for (int i=tid; i<73728/4; i+=1024) ((unsigned*)(sm + S0HI))[i] = 0u;
    float* sbias = (float*)(sm + BIASO);
    if (tid < 64){
        int j = tid;
        sbias[j]     = bih0[j]    + bhh0[j];
        sbias[64+j]  = bih0[64+j] + bhh0[64+j];
        sbias[128+j] = bih0[128+j];
        sbias[192+j] = bhh0[128+j];
        sbias[256+j] = bih1[j]    + bhh1[j];
        sbias[320+j] = bih1[64+j] + bhh1[64+j];
        sbias[384+j] = bih1[128+j];
        sbias[448+j] = bhh1[128+j];
    }
    __syncthreads();

    const int lane = tid & 31, warp = tid >> 5;
    const int grp = warp & 3;            // SMSP id == group
    const int role = warp >> 2;          // 0-3: L0 quarters; 4-7: L1 quarters
    const int quarter = role & 3;
    const int rquad = lane >> 2, c = lane & 3;
    const int row0 = blockIdx.x*64 + grp*16 + rquad;
    const unsigned smb = smem_u32(sm);
    const int sub = lane >> 3, r8 = lane & 7;
    const unsigned soff = r8*144 + sub*16;
    const unsigned a_w0 = smb + W0HI  + soff;
    const unsigned a_i1 = smb + WI1HI + soff;
    const unsigned a_h1 = smb + WH1HI + soff;
    const unsigned xgrow = (sub==0) ? 0u : (sub==1 ? 64u : 128u);
    const unsigned a_x = smb + XWHI + (xgrow + r8)*16;

    const unsigned lsl = (lane & 15)*144 + (lane >> 4)*16;
    const unsigned stb = grp*2304 + rquad*144 + 4*c;

    #pragma unroll 1
    for (int it=0; it<=TT; it++){
        if (role < 4 && it < TT){
            const int t = it;
            const unsigned rd = (unsigned)(((t+1)&1)*9216);
            const unsigned wr = (unsigned)((t&1)*9216);
            unsigned a0h[4][4], a0l[4][4];
            #pragma unroll
            for (int kt=0;kt<4;kt++){
                LDSM4A(a0h[kt], smb + S0HI + rd + grp*2304 + lsl + kt*32);
                LDSM4A(a0l[kt], smb + S0LO + rd + grp*2304 + lsl + kt*32);
            }
            const float* _xp = g_xt + ((size_t)t*NN + row0)*8 + 2*c;
            float2 _x0 = *(const float2*)_xp;
            float2 _x1 = *(const float2*)(_xp + 64);
            unsigned xh0 = pk2h(hfr(_x0.x), hfr(_x0.y));
            unsigned xh1 = pk2h(hfr(_x1.x), hfr(_x1.y));
            unsigned xl0 = pk2h(_x0.x-hfr(_x0.x), _x0.y-hfr(_x0.y));
            unsigned xl1 = pk2h(_x1.x-hfr(_x1.x), _x1.y-hfr(_x1.y));
            const unsigned st0h = smb + S0HI + wr + stb;
            const unsigned st0l = smb + S0LO + wr + stb;
            switch (quarter){
                case 0: { L0_TILE(0, xh0,xh1,xl0,xl1); L0_TILE(1, xh0,xh1,xl0,xl1); } break;
                case 1: { L0_TILE(2, xh0,xh1,xl0,xl1); L0_TILE(3, xh0,xh1,xl0,xl1); } break;
                case 2: { L0_TILE(4, xh0,xh1,xl0,xl1); L0_TILE(5, xh0,xh1,xl0,xl1); } break;
                default:{ L0_TILE(6, xh0,xh1,xl0,xl1); L0_TILE(7, xh0,xh1,xl0,xl1); } break;
            }
        }
        if (role >= 4 && it >= 1){
            const int t = it - 1;
            const unsigned rd0 = (unsigned)((t&1)*9216);        // h0(t), written by L0 last iter
            const unsigned rd1 = (unsigned)(((t+1)&1)*9216);    // h1(t-1)
            const unsigned wr1 = (unsigned)((t&1)*9216);        // h1(t)
            unsigned yh[4][4], yl[4][4], a1h[4][4], a1l[4][4];
            #pragma unroll
            for (int kt=0;kt<4;kt++){
                LDSM4A(yh[kt],  smb + S0HI + rd0 + grp*2304 + lsl + kt*32);
                LDSM4A(yl[kt],  smb + S0LO + rd0 + grp*2304 + lsl + kt*32);
                LDSM4A(a1h[kt], smb + S1HI + rd1 + grp*2304 + lsl + kt*32);
                LDSM4A(a1l[kt], smb + S1LO + rd1 + grp*2304 + lsl + kt*32);
            }
            const unsigned st1h = smb + S1HI + wr1 + stb;
            const unsigned st1l = smb + S1LO + wr1 + stb;
            switch (quarter){
                case 0: { L1_TILE(0); L1_TILE(1); } break;
                case 1: { L1_TILE(2); L1_TILE(3); } break;
                case 2: { L1_TILE(4); L1_TILE(5); } break;
                default:{ L1_TILE(6); L1_TILE(7); } break;
            }
        }
        __syncthreads();
    }

    // final h1 = buffer of t=59 -> (59&1)=1
    if (role == 7){
        const char* p1h = sm + S1HI + 9216 + grp*2304;
        const char* p1l = sm + S1LO + 9216 + grp*2304;
        for (int i=lane; i<16*32; i+=32){
            int row = i>>5, cp = i&31;
            unsigned vh = *(const unsigned*)(p1h + row*144 + cp*4);
            unsigned vl = *(const unsigned*)(p1l + row*144 + cp*4);
            float2 a = uhf2(vh), b = uhf2(vl);
            float2 v; v.x = a.x + b.x; v.y = a.y + b.y;
            *(float2*)(g_hidden + (size_t)(blockIdx.x*64 + grp*16 + row)*64 + cp*2) = v;
        }
    }
}

__global__ __launch_bounds__(512) void post_kernel(
    const float* __restrict__ trW, const float* __restrict__ trb, const float* __restrict__ a)
{
    __shared__ float sWt[HH*HH];
    __shared__ float sh[8*HH];
    __shared__ float sa[2*HH];
    __shared__ float sred[16][2];
    int tid = threadIdx.x;
    for (int idx=tid; idx<HH*HH; idx+=512){ int o=idx>>6, k=idx&63; sWt[k*HH+o]=trW[idx]; }
    if (tid < 2*HH) sa[tid] = a[tid];
    int lr = tid>>6, j = tid&63;
    int i = blockIdx.x*8 + lr;
    sh[lr*HH+j] = g_hidden[i*HH+j];
    __syncthreads();
    float acc = trb[j];
    #pragma unroll 8
    for (int k=0; k<HH; k++) acc += sWt[k*HH+j]*sh[lr*HH+k];
    float p1 = acc*sa[j], p2 = acc*sa[HH+j];
    #pragma unroll
    for (int off=16; off; off>>=1){
        p1 += __shfl_down_sync(0xffffffffu, p1, off);
        p2 += __shfl_down_sync(0xffffffffu, p2, off);
    }
    int wid = tid>>5;
    if ((tid&31)==0){ sred[wid][0]=p1; sred[wid][1]=p2; }
    __syncthreads();
    if (tid < 8){
        float s1 = sred[2*tid][0] + sred[2*tid+1][0];
        float s2 = sred[2*tid][1] + sred[2*tid+1][1];
        int n = blockIdx.x*8 + tid;
        g_s1[n] = s1; g_s2[n] = s2;
        unsigned u = __float_as_uint(s1);
        u = (u & 0x80000000u) ? ~u : (u | 0x80000000u);
        g_keys[n] = ((unsigned long long)u << 32) | (unsigned)n;
    }
}

__global__ __launch_bounds__(1024) void sort_kernel(){
    extern __shared__ unsigned long long sk[];
    int tid = threadIdx.x;
    for (int i=tid; i<NN; i+=1024) sk[i] = g_keys[i];
    __syncthreads();
    for (int k=2; k<=NN; k<<=1){
        for (int j=k>>1; j>0; j>>=1){
            for (int i=tid; i<NN; i+=1024){
                int ixj = i^j;
                if (ixj > i){
                    unsigned long long va = sk[i], vb = sk[ixj];
                    bool up = ((i & k) == 0);
                    if ((va > vb) == up){ sk[i]=vb; sk[ixj]=va; }
                }
            }
            __syncthreads();
        }
    }
    for (int r=tid; r<NN; r+=1024){
        unsigned long long key = sk[r];
        int idx = (int)(key & 0xffffffffu);
        g_perm[r] = idx;
        g_s1s[r]  = g_s1[idx];
    }
}

__global__ __launch_bounds__(256) void exp_kernel(){
    int i = blockIdx.x*256 + threadIdx.x;
    double v = (double)g_s1s[i];
    g_e1[i]  = exp(v);
    g_e01[i] = exp(0.01*v);
}

__global__ __launch_bounds__(1024) void scan_kernel(){
    __shared__ double ssum[1024];
    int c = blockIdx.x, tid = threadIdx.x;
    int nscans = (c == 128) ? 2 : 1;
    for (int s=0; s<nscans; s++){
        double local[8], ts = 0.0;
        #pragma unroll
        for (int e=0; e<8; e++){
            int r = tid*8 + e;
            double w;
            if (c < 64)       w = g_e1[r]  * (double)g_hidden[g_perm[r]*HH + c];
            else if (c < 128) w = g_e01[r] * (double)g_hidden[g_perm[r]*HH + (c-64)];
            else              w = (s == 0) ? g_e1[r] : g_e01[r];
            local[e] = w; ts += w;
        }
        ssum[tid] = ts; __syncthreads();
        for (int off=1; off<1024; off<<=1){
            double v = ssum[tid];
            if (tid >= off) v += ssum[tid-off];
            __syncthreads(); ssum[tid] = v; __syncthreads();
        }
        double run = tid ? ssum[tid-1] : 0.0;
        #pragma unroll
        for (int e=0; e<8; e++){
            int r = tid*8 + e;
            if (c < 64)       g_prefP[r*HH + c]      = run;
            else if (c < 128) g_prefQ[r*HH + (c-64)] = run;
            else              g_prefE[r*2 + s]        = run;
            run += local[e];
        }
        if (tid == 1023){
            double tot = ssum[1023];
            if (c < 64)       g_prefP[NN*HH + c]      = tot;
            else if (c < 128) g_prefQ[NN*HH + (c-64)] = tot;
            else              g_prefE[NN*2 + s]        = tot;
        }
        __syncthreads();
    }
}

__global__ __launch_bounds__(256) void final_kernel(
    const float* __restrict__ fcW, const float* __restrict__ fcb,
    const float* __restrict__ outW, const float* __restrict__ outb,
    float* __restrict__ out)
{
    __shared__ float sFcT[HH*HH];
    __shared__ float sOw[HH], sFb[HH];
    __shared__ float sH[8][HH];
    int tid = threadIdx.x;
    for (int idx=tid; idx<HH*HH; idx+=256){ int o=idx>>6, k=idx&63; sFcT[k*HH+o]=fcW[idx]; }
    if (tid < HH){ sOw[tid]=outW[tid]; sFb[tid]=fcb[tid]; }
    int w = tid>>5, lane = tid&31;
    int i = blockIdx.x*8 + w;
    float s2 = g_s2[i];
    float thr = -s2;
    int lo = 0, hi = NN;
    while (lo < hi){ int mid = (lo+hi)>>1; if (g_s1s[mid] < thr) lo = mid+1; else hi = mid; }
    int m = lo;
    double e2p = exp((double)s2), e2n = exp(0.01*(double)s2);
    double den = e2p*(g_prefE[NN*2+0] - g_prefE[m*2+0]) + e2n*g_prefE[m*2+1];
    __syncthreads();
    #pragma unroll
    for (int q=0; q<2; q++){
        int d = lane + q*32;
        double Pt = g_prefP[NN*HH + d];
        double num = e2p*(Pt - g_prefP[m*HH + d]) + e2n*g_prefQ[m*HH + d];
        sH[w][d] = (float)(num/den) + g_hidden[i*HH + d];
    }
    __syncwarp();
    float partial = 0.f;
    #pragma unroll
    for (int q=0; q<2; q++){
        int o = lane + q*32;
        float acc = sFb[o];
        #pragma unroll 8
        for (int k=0; k<HH; k++) acc += sFcT[k*HH+o]*sH[w][k];
        acc = (acc >= 0.f) ? acc : 0.01f*acc;
        partial += acc*sOw[o];
    }
    #pragma unroll
    for (int off=16; off; off>>=1) partial += __shfl_down_sync(0xffffffffu, partial, off);
    if (lane == 0) out[i] = partial + outb[0];
}

extern "C" void kernel_launch(void* const* d_in, const int* in_sizes, int n_in,
                              void* d_out, int out_size)
{
    const float* x    = (const float*)d_in[0];
    const float* Wih0 = (const float*)d_in[1];
    const float* Whh0 = (const float*)d_in[2];
    const float* bih0 = (const float*)d_in[3];
    const float* bhh0 = (const float*)d_in[4];
    const float* Wih1 = (const float*)d_in[5];
    const float* Whh1 = (const float*)d_in[6];
    const float* bih1 = (const float*)d_in[7];
    const float* bhh1 = (const float*)d_in[8];
    const float* trW  = (const float*)d_in[9];
    const float* trb  = (const float*)d_in[10];
    const float* a    = (const float*)d_in[11];
    const float* fcW  = (const float*)d_in[12];
    const float* fcb  = (const float*)d_in[13];
    const float* outW = (const float*)d_in[14];
    const float* outb = (const float*)d_in[15];

    cudaFuncSetAttribute(gru_kernel,  cudaFuncAttributeMaxDynamicSharedMemorySize, SMEM_GRU);
    cudaFuncSetAttribute(sort_kernel, cudaFuncAttributeMaxDynamicSharedMemorySize, 65536);

    transpose_kernel<<<NN/32, 256>>>(x);
    gru_kernel<<<128, 1024, SMEM_GRU>>>(Wih0, Whh0, bih0, bhh0, Wih1, Whh1, bih1, bhh1);
    post_kernel<<<NN/8, 512>>>(trW, trb, a);
    sort_kernel<<<1, 1024, 65536>>>();
    exp_kernel<<<NN/256, 256>>>();
    scan_kernel<<<129, 1024>>>();
    final_kernel<<<NN/8, 256>>>(fcW, fcb, outW, outb, (float*)d_out);
}

// round 13
// speedup vs baseline: 1.4369x; 1.4369x over previous
#include <cuda_runtime.h>
#include <cuda_fp16.h>
#include <math.h>

#define NN 8192
#define TT 60
#define HH 64

__device__ float g_xt[(size_t)TT*NN*8];
__device__ float g_hidden[NN*HH];
__device__ float g_s1[NN];
__device__ float g_s2[NN];
__device__ unsigned g_keys32[NN];
__device__ unsigned g_ksort[NN];
__device__ float g_s1s[NN];
__device__ int   g_perm[NN];
__device__ double g_e1[NN];
__device__ double g_e01[NN];
__device__ double g_prefP[(NN+1)*HH];
__device__ double g_prefQ[(NN+1)*HH];
__device__ double g_prefE[(NN+1)*2];

__device__ __forceinline__ float sig_f(float x){ return 1.f/(1.f+__expf(-x)); }
__device__ __forceinline__ float tanh_f(float x){ return 1.f-2.f/(__expf(2.f*x)+1.f); }
__device__ __forceinline__ unsigned f2u(float f){
    unsigned u = __float_as_uint(f);
    return (u & 0x80000000u) ? ~u : (u | 0x80000000u);
}

__device__ __forceinline__ unsigned pk2h(float lo, float hi){
    unsigned r;
    asm("{.reg .b16 l,h;\n cvt.rn.f16.f32 l, %1;\n cvt.rn.f16.f32 h, %2;\n mov.b32 %0, {l,h};}"
        : "=r"(r) : "f"(lo), "f"(hi));
    return r;
}
__device__ __forceinline__ float hfr(float v){
    float o;
    asm("{.reg .b16 t;\n cvt.rn.f16.f32 t, %1;\n cvt.f32.f16 %0, t;}" : "=f"(o) : "f"(v));
    return o;
}
__device__ __forceinline__ unsigned short h16(float v){
    unsigned short s;
    asm("{.reg .b16 t;\n cvt.rn.f16.f32 t, %1;\n mov.b16 %0, t;}" : "=h"(s) : "f"(v));
    return s;
}
__device__ __forceinline__ float2 uhf2(unsigned u){
    float2 f;
    asm("{.reg .b16 l,h;\n mov.b32 {l,h}, %2;\n cvt.f32.f16 %0, l;\n cvt.f32.f16 %1, h;}"
        : "=f"(f.x), "=f"(f.y) : "r"(u));
    return f;
}

#define MMA16(C, A, B0, B1) \
    asm("mma.sync.aligned.m16n8k16.row.col.f32.f16.f16.f32 " \
        "{%0,%1,%2,%3},{%4,%5,%6,%7},{%8,%9},{%0,%1,%2,%3};" \
        : "+f"(C[0]),"+f"(C[1]),"+f"(C[2]),"+f"(C[3]) \
        : "r"((A)[0]),"r"((A)[1]),"r"((A)[2]),"r"((A)[3]),"r"(B0),"r"(B1))

#define MMA8(C, A0, A1, B0) \
    asm("mma.sync.aligned.m16n8k8.row.col.f32.f16.f16.f32 " \
        "{%0,%1,%2,%3},{%4,%5},{%6},{%0,%1,%2,%3};" \
        : "+f"(C[0]),"+f"(C[1]),"+f"(C[2]),"+f"(C[3]) \
        : "r"(A0),"r"(A1),"r"(B0))

#define LDSM4(Q, ADDR) \
    asm volatile("ldmatrix.sync.aligned.m8n8.x4.shared.b16 {%0,%1,%2,%3},[%4];" \
        : "=r"(Q.x),"=r"(Q.y),"=r"(Q.z),"=r"(Q.w) : "r"(ADDR))

#define LDSM4A(A, ADDR) \
    asm volatile("ldmatrix.sync.aligned.m8n8.x4.shared.b16 {%0,%1,%2,%3},[%4];" \
        : "=r"((A)[0]),"=r"((A)[1]),"=r"((A)[2]),"=r"((A)[3]) : "r"(ADDR) : "memory")

#define STS32(ADDR, V) \
    asm volatile("st.shared.u32 [%0], %1;" :: "r"(ADDR), "r"(V) : "memory")

// smem byte offsets (S0 and S1 both double-buffered: 2 x 9216 each region)
#define XWHI 0
#define W0HI 3072
#define WI1HI 30720
#define WH1HI 58368
#define BIASO 86016
#define S0HI 88064
#define S0LO 106496
#define S1HI 124928
#define S1LO 143360
#define SMEM_GRU 161792

__device__ __forceinline__ unsigned smem_u32(const void* p){
    unsigned a; asm("{ .reg .u64 t; cvta.to.shared.u64 t, %1; cvt.u32.u64 %0, t; }" : "=r"(a) : "l"(p));
    return a;
}

#define GATE_EPI2(Cr,Cz,Ci,Chn, BOFF, n0_, AHI, ALO, i0_, SH_, SL_) do{ \
    float2 _br = *(const float2*)(sbias + (BOFF) + (n0_) + 2*c); \
    float2 _bz = *(const float2*)(sbias + (BOFF) + 64 + (n0_) + 2*c); \
    float2 _bi = *(const float2*)(sbias + (BOFF) + 128 + (n0_) + 2*c); \
    float2 _bh = *(const float2*)(sbias + (BOFF) + 192 + (n0_) + 2*c); \
    float2 _p0 = uhf2((AHI)[i0_]),   _q0 = uhf2((ALO)[i0_]); \
    float2 _p1 = uhf2((AHI)[i0_+1]), _q1 = uhf2((ALO)[i0_+1]); \
    float _hp0=_p0.x+_q0.x, _hp1=_p0.y+_q0.y, _hp2=_p1.x+_q1.x, _hp3=_p1.y+_q1.y; \
    float _r0=sig_f(Cr[0]+_br.x), _r1=sig_f(Cr[1]+_br.y), _r2=sig_f(Cr[2]+_br.x), _r3=sig_f(Cr[3]+_br.y); \
    float _z0=sig_f(Cz[0]+_bz.x), _z1=sig_f(Cz[1]+_bz.y), _z2=sig_f(Cz[2]+_bz.x), _z3=sig_f(Cz[3]+_bz.y); \
    float _n0=tanh_f(Ci[0]+_bi.x+_r0*(Chn[0]+_bh.x)); \
    float _n1=tanh_f(Ci[1]+_bi.y+_r1*(Chn[1]+_bh.y)); \
    float _n2=tanh_f(Ci[2]+_bi.x+_r2*(Chn[2]+_bh.x)); \
    float _n3=tanh_f(Ci[3]+_bi.y+_r3*(Chn[3]+_bh.y)); \
    float _h0=_n0+_z0*(_hp0-_n0), _h1=_n1+_z1*(_hp1-_n1); \
    float _h2=_n2+_z2*(_hp2-_n2), _h3=_n3+_z3*(_hp3-_n3); \
    STS32((SH_) + (n0_)*2,        pk2h(_h0,_h1)); \
    STS32((SH_) + (n0_)*2 + 1152, pk2h(_h2,_h3)); \
    STS32((SL_) + (n0_)*2,        pk2h(_h0-hfr(_h0), _h1-hfr(_h1))); \
    STS32((SL_) + (n0_)*2 + 1152, pk2h(_h2-hfr(_h2), _h3-hfr(_h3))); \
}while(0)

#define L0_TILE(t8, XH0,XH1,XL0,XL1) do{ \
    const int n0 = (t8)*8; \
    float Cr[4]={0,0,0,0}, Cz[4]={0,0,0,0}, Ci[4]={0,0,0,0}, Chn[4]={0,0,0,0}; \
    uint4 qx; LDSM4(qx, a_x + n0*16); \
    MMA8(Cr,XH0,XH1,qx.x); MMA8(Cz,XH0,XH1,qx.y); MMA8(Ci,XH0,XH1,qx.z); \
    MMA8(Cr,XL0,XL1,qx.x); MMA8(Cz,XL0,XL1,qx.y); MMA8(Ci,XL0,XL1,qx.z); \
    _Pragma("unroll") \
    for (int kp=0; kp<2; kp++){ \
        uint4 qr, qz, qn; \
        LDSM4(qr, a_w0 + n0*144 + kp*64); \
        LDSM4(qz, a_w0 + 9216 + n0*144 + kp*64); \
        LDSM4(qn, a_w0 + 18432 + n0*144 + kp*64); \
        const int k0 = 2*kp; \
        MMA16(Cr, a0h[k0], qr.x, qr.y); MMA16(Cz, a0h[k0], qz.x, qz.y); MMA16(Chn, a0h[k0], qn.x, qn.y); \
        MMA16(Cr, a0l[k0], qr.x, qr.y); MMA16(Cz, a0l[k0], qz.x, qz.y); MMA16(Chn, a0l[k0], qn.x, qn.y); \
        MMA16(Cr, a0h[k0+1], qr.z, qr.w); MMA16(Cz, a0h[k0+1], qz.z, qz.w); MMA16(Chn, a0h[k0+1], qn.z, qn.w); \
        MMA16(Cr, a0l[k0+1], qr.z, qr.w); MMA16(Cz, a0l[k0+1], qz.z, qz.w); MMA16(Chn, a0l[k0+1], qn.z, qn.w); \
    } \
    const int kt0 = (t8)>>1, i0 = ((t8)&1)*2; \
    GATE_EPI2(Cr,Cz,Ci,Chn, 0, n0, a0h[kt0], a0l[kt0], i0, st0h, st0l); \
}while(0)

#define L1_TILE(t8) do{ \
    const int n0 = (t8)*8; \
    float Cri[4]={0,0,0,0}, Crh[4]={0,0,0,0}, Czi[4]={0,0,0,0}, Czh[4]={0,0,0,0}; \
    float Cii[4]={0,0,0,0}, Chn[4]={0,0,0,0}; \
    _Pragma("unroll") \
    for (int kp=0; kp<2; kp++){ \
        uint4 q0,q1,q2,q3,q4,q5; \
        LDSM4(q0, a_i1 + n0*144 + kp*64); \
        LDSM4(q1, a_h1 + n0*144 + kp*64); \
        LDSM4(q2, a_i1 + 9216 + n0*144 + kp*64); \
        LDSM4(q3, a_h1 + 9216 + n0*144 + kp*64); \
        LDSM4(q4, a_i1 + 18432 + n0*144 + kp*64); \
        LDSM4(q5, a_h1 + 18432 + n0*144 + kp*64); \
        const int k0 = 2*kp; \
        MMA16(Cri, yh[k0], q0.x, q0.y); MMA16(Crh, a1h[k0], q1.x, q1.y); \
        MMA16(Czi, yh[k0], q2.x, q2.y); MMA16(Czh, a1h[k0], q3.x, q3.y); \
        MMA16(Cii, yh[k0], q4.x, q4.y); MMA16(Chn, a1h[k0], q5.x, q5.y); \
        MMA16(Cri, yl[k0], q0.x, q0.y); MMA16(Crh, a1l[k0], q1.x, q1.y); \
        MMA16(Czi, yl[k0], q2.x, q2.y); MMA16(Czh, a1l[k0], q3.x, q3.y); \
        MMA16(Cii, yl[k0], q4.x, q4.y); MMA16(Chn, a1l[k0], q5.x, q5.y); \
        MMA16(Cri, yh[k0+1], q0.z, q0.w); MMA16(Crh, a1h[k0+1], q1.z, q1.w); \
        MMA16(Czi, yh[k0+1], q2.z, q2.w); MMA16(Czh, a1h[k0+1], q3.z, q3.w); \
        MMA16(Cii, yh[k0+1], q4.z, q4.w); MMA16(Chn, a1h[k0+1], q5.z, q5.w); \
        MMA16(Cri, yl[k0+1], q0.z, q0.w); MMA16(Crh, a1l[k0+1], q1.z, q1.w); \
        MMA16(Czi, yl[k0+1], q2.z, q2.w); MMA16(Czh, a1l[k0+1], q3.z, q3.w); \
        MMA16(Cii, yl[k0+1], q4.z, q4.w); MMA16(Chn, a1l[k0+1], q5.z, q5.w); \
    } \
    float Cr[4], Cz[4]; \
    _Pragma("unroll") \
    for (int i=0;i<4;i++){ Cr[i]=Cri[i]+Crh[i]; Cz[i]=Czi[i]+Czh[i]; } \
    const int kt0 = (t8)>>1, i0 = ((t8)&1)*2; \
    GATE_EPI2(Cr,Cz,Cii,Chn, 256, n0, a1h[kt0], a1l[kt0], i0, st1h, st1l); \
}while(0)

__global__ __launch_bounds__(256) void transpose_kernel(const float* __restrict__ x){
    __shared__ float sx[32*360];
    int nb = blockIdx.x*32, tid = threadIdx.x;
    for (int idx=tid; idx<32*360; idx+=256) sx[idx] = x[(size_t)nb*360 + idx];
    __syncthreads();
    int n = tid>>3, d = tid&7;
    float* op = g_xt + ((size_t)(nb+n))*8 + d;
    #pragma unroll 4
    for (int t=0; t<TT; t++)
        op[(size_t)t*NN*8] = (d<6) ? sx[n*360 + d*60 + t] : 0.f;
}

__global__ __launch_bounds__(512,1) void gru_kernel(
    const float* __restrict__ Wih0, const float* __restrict__ Whh0,
    const float* __restrict__ bih0, const float* __restrict__ bhh0,
    const float* __restrict__ Wih1, const float* __restrict__ Whh1,
    const float* __restrict__ bih1, const float* __restrict__ bhh1)
{
    extern __shared__ char sm[];
    const int tid = threadIdx.x;
    unsigned short* xw = (unsigned short*)(sm + XWHI);
    for (int i=tid; i<1536; i+=512) xw[i]=0;
    for (int i=tid; i<1152; i+=512){
        int n = i/6, d = i - n*6;
        xw[n*8+d] = h16(Wih0[i]);
    }
    {
        unsigned short* w0 = (unsigned short*)(sm + W0HI);
        unsigned short* i1 = (unsigned short*)(sm + WI1HI);
        unsigned short* h1 = (unsigned short*)(sm + WH1HI);
        for (int i=tid; i<12288; i+=512){
            int n = i>>6, k = i&63, o = n*72+k;
            w0[o] = h16(Whh0[i]);
            i1[o] = h16(Wih1[i]);
            h1[o] = h16(Whh1[i]);
        }
    }
    for (int i=tid; i<73728/4; i+=512) ((unsigned*)(sm + S0HI))[i] = 0u;
    float* sbias = (float*)(sm + BIASO);
    if (tid < 64){
        int j = tid;
        sbias[j]     = bih0[j]    + bhh0[j];
        sbias[64+j]  = bih0[64+j] + bhh0[64+j];
        sbias[128+j] = bih0[128+j];
        sbias[192+j] = bhh0[128+j];
        sbias[256+j] = bih1[j]    + bhh1[j];
        sbias[320+j] = bih1[64+j] + bhh1[64+j];
        sbias[384+j] = bih1[128+j];
        sbias[448+j] = bhh1[128+j];
    }
    __syncthreads();

    const int lane = tid & 31, warp = tid >> 5;
    const int grp = warp & 3;            // SMSP id == group
    const int role = warp >> 2;          // 0,1: L0 halves; 2,3: L1 halves
    const int half = role & 1;
    const int rquad = lane >> 2, c = lane & 3;
    const int row0 = blockIdx.x*64 + grp*16 + rquad;
    const unsigned smb = smem_u32(sm);
    const int sub = lane >> 3, r8 = lane & 7;
    const unsigned soff = r8*144 + sub*16;
    const unsigned a_w0 = smb + W0HI  + soff;
    const unsigned a_i1 = smb + WI1HI + soff;
    const unsigned a_h1 = smb + WH1HI + soff;
    const unsigned xgrow = (sub==0) ? 0u : (sub==1 ? 64u : 128u);
    const unsigned a_x = smb + XWHI + (xgrow + r8)*16;

    const unsigned lsl = (lane & 15)*144 + (lane >> 4)*16;
    const unsigned stb = grp*2304 + rquad*144 + 4*c;

    #pragma unroll 1
    for (int it=0; it<=TT; it++){
        if (role < 2 && it < TT){
            const int t = it;
            const unsigned rd = (unsigned)(((t+1)&1)*9216);
            const unsigned wr = (unsigned)((t&1)*9216);
            unsigned a0h[4][4], a0l[4][4];
            #pragma unroll
            for (int kt=0;kt<4;kt++){
                LDSM4A(a0h[kt], smb + S0HI + rd + grp*2304 + lsl + kt*32);
                LDSM4A(a0l[kt], smb + S0LO + rd + grp*2304 + lsl + kt*32);
            }
            const float* _xp = g_xt + ((size_t)t*NN + row0)*8 + 2*c;
            float2 _x0 = *(const float2*)_xp;
            float2 _x1 = *(const float2*)(_xp + 64);
            unsigned xh0 = pk2h(hfr(_x0.x), hfr(_x0.y));
            unsigned xh1 = pk2h(hfr(_x1.x), hfr(_x1.y));
            unsigned xl0 = pk2h(_x0.x-hfr(_x0.x), _x0.y-hfr(_x0.y));
            unsigned xl1 = pk2h(_x1.x-hfr(_x1.x), _x1.y-hfr(_x1.y));
            const unsigned st0h = smb + S0HI + wr + stb;
            const unsigned st0l = smb + S0LO + wr + stb;
            if (!half){
                #pragma unroll
                for (int t8=0; t8<4; t8++) L0_TILE(t8, xh0,xh1,xl0,xl1);
            } else {
                #pragma unroll
                for (int t8=4; t8<8; t8++) L0_TILE(t8, xh0,xh1,xl0,xl1);
            }
        }
        if (role >= 2 && it >= 1){
            const int t = it - 1;
            const unsigned rd0 = (unsigned)((t&1)*9216);        // h0(t), written by L0 last iter
            const unsigned rd1 = (unsigned)(((t+1)&1)*9216);    // h1(t-1)
            const unsigned wr1 = (unsigned)((t&1)*9216);        // h1(t)
            unsigned yh[4][4], yl[4][4], a1h[4][4], a1l[4][4];
            #pragma unroll
            for (int kt=0;kt<4;kt++){
                LDSM4A(yh[kt],  smb + S0HI + rd0 + grp*2304 + lsl + kt*32);
                LDSM4A(yl[kt],  smb + S0LO + rd0 + grp*2304 + lsl + kt*32);
                LDSM4A(a1h[kt], smb + S1HI + rd1 + grp*2304 + lsl + kt*32);
                LDSM4A(a1l[kt], smb + S1LO + rd1 + grp*2304 + lsl + kt*32);
            }
            const unsigned st1h = smb + S1HI + wr1 + stb;
            const unsigned st1l = smb + S1LO + wr1 + stb;
            if (!half){
                #pragma unroll
                for (int t8=0; t8<4; t8++) L1_TILE(t8);
            } else {
                #pragma unroll
                for (int t8=4; t8<8; t8++) L1_TILE(t8);
            }
        }
        __syncthreads();
    }

    // final h1 = buffer of t=59 -> (59&1)=1
    if (role == 3){
        const char* p1h = sm + S1HI + 9216 + grp*2304;
        const char* p1l = sm + S1LO + 9216 + grp*2304;
        for (int i=lane; i<16*32; i+=32){
            int row = i>>5, cp = i&31;
            unsigned vh = *(const unsigned*)(p1h + row*144 + cp*4);
            unsigned vl = *(const unsigned*)(p1l + row*144 + cp*4);
            float2 a = uhf2(vh), b = uhf2(vl);
            float2 v; v.x = a.x + b.x; v.y = a.y + b.y;
            *(float2*)(g_hidden + (size_t)(blockIdx.x*64 + grp*16 + row)*64 + cp*2) = v;
        }
    }
}

__global__ __launch_bounds__(512) void post_kernel(
    const float* __restrict__ trW, const float* __restrict__ trb, const float* __restrict__ a)
{
    __shared__ float sWt[HH*HH];
    __shared__ float sh[8*HH];
    __shared__ float sa[2*HH];
    __shared__ float sred[16][2];
    int tid = threadIdx.x;
    for (int idx=tid; idx<HH*HH; idx+=512){ int o=idx>>6, k=idx&63; sWt[k*HH+o]=trW[idx]; }
    if (tid < 2*HH) sa[tid] = a[tid];
    int lr = tid>>6, j = tid&63;
    int i = blockIdx.x*8 + lr;
    sh[lr*HH+j] = g_hidden[i*HH+j];
    __syncthreads();
    float acc = trb[j];
    #pragma unroll 8
    for (int k=0; k<HH; k++) acc += sWt[k*HH+j]*sh[lr*HH+k];
    float p1 = acc*sa[j], p2 = acc*sa[HH+j];
    #pragma unroll
    for (int off=16; off; off>>=1){
        p1 += __shfl_down_sync(0xffffffffu, p1, off);
        p2 += __shfl_down_sync(0xffffffffu, p2, off);
    }
    int wid = tid>>5;
    if ((tid&31)==0){ sred[wid][0]=p1; sred[wid][1]=p2; }
    __syncthreads();
    if (tid < 8){
        float s1 = sred[2*tid][0] + sred[2*tid+1][0];
        float s2 = sred[2*tid][1] + sred[2*tid+1][1];
        int n = blockIdx.x*8 + tid;
        g_s1[n] = s1; g_s2[n] = s2;
        unsigned u = f2u(s1);
        g_keys32[n] = ((u >> 13) << 13) | (unsigned)n;
    }
}

__global__ __launch_bounds__(1024) void sort_kernel(){
    extern __shared__ unsigned sk32[];
    int tid = threadIdx.x;
    for (int i=tid; i<NN; i+=1024) sk32[i] = g_keys32[i];
    __syncthreads();
    for (int k=2; k<=NN; k<<=1){
        for (int j=k>>1; j>0; j>>=1){
            for (int i=tid; i<NN; i+=1024){
                int ixj = i^j;
                if (ixj > i){
                    unsigned va = sk32[i], vb = sk32[ixj];
                    bool up = ((i & k) == 0);
                    if ((va > vb) == up){ sk32[i]=vb; sk32[ixj]=va; }
                }
            }
            __syncthreads();
        }
    }
    for (int r=tid; r<NN; r+=1024){
        unsigned key = sk32[r];
        int idx = (int)(key & 8191u);
        g_perm[r]  = idx;
        g_s1s[r]   = g_s1[idx];
        g_ksort[r] = key;
    }
}

__global__ __launch_bounds__(256) void exp_kernel(){
    int i = blockIdx.x*256 + threadIdx.x;
    double v = (double)g_s1s[i];
    g_e1[i]  = exp(v);
    g_e01[i] = exp(0.01*v);
}

__global__ __launch_bounds__(1024) void scan_kernel(){
    __shared__ double ssum[1024];
    int c = blockIdx.x, tid = threadIdx.x;
    int nscans = (c == 128) ? 2 : 1;
    for (int s=0; s<nscans; s++){
        double local[8], ts = 0.0;
        #pragma unroll
        for (int e=0; e<8; e++){
            int r = tid*8 + e;
            double w;
            if (c < 64)       w = g_e1[r]  * (double)g_hidden[g_perm[r]*HH + c];
            else if (c < 128) w = g_e01[r] * (double)g_hidden[g_perm[r]*HH + (c-64)];
            else              w = (s == 0) ? g_e1[r] : g_e01[r];
            local[e] = w; ts += w;
        }
        ssum[tid] = ts; __syncthreads();
        for (int off=1; off<1024; off<<=1){
            double v = ssum[tid];
            if (tid >= off) v += ssum[tid-off];
            __syncthreads(); ssum[tid] = v; __syncthreads();
        }
        double run = tid ? ssum[tid-1] : 0.0;
        #pragma unroll
        for (int e=0; e<8; e++){
            int r = tid*8 + e;
            if (c < 64)       g_prefP[r*HH + c]      = run;
            else if (c < 128) g_prefQ[r*HH + (c-64)] = run;
            else              g_prefE[r*2 + s]        = run;
            run += local[e];
        }
        if (tid == 1023){
            double tot = ssum[1023];
            if (c < 64)       g_prefP[NN*HH + c]      = tot;
            else if (c < 128) g_prefQ[NN*HH + (c-64)] = tot;
            else              g_prefE[NN*2 + s]        = tot;
        }
        __syncthreads();
    }
}

__global__ __launch_bounds__(256) void final_kernel(
    const float* __restrict__ fcW, const float* __restrict__ fcb,
    const float* __restrict__ outW, const float* __restrict__ outb,
    float* __restrict__ out)
{
    __shared__ float sFcT[HH*HH];
    __shared__ float sOw[HH], sFb[HH];
    __shared__ float sH[8][HH];
    int tid = threadIdx.x;
    for (int idx=tid; idx<HH*HH; idx+=256){ int o=idx>>6, k=idx&63; sFcT[k*HH+o]=fcW[idx]; }
    if (tid < HH){ sOw[tid]=outW[tid]; sFb[tid]=fcb[tid]; }
    int w = tid>>5, lane = tid&31;
    int i = blockIdx.x*8 + w;
    float s2 = g_s2[i];
    // threshold key: elements with key19(s1) >= key19(-s2) take the >=0 branch
    unsigned thrkey = (f2u(-s2) >> 13) << 13;
    int lo = 0, hi = NN;
    while (lo < hi){ int mid = (lo+hi)>>1; if (g_ksort[mid] < thrkey) lo = mid+1; else hi = mid; }
    int m = lo;
    double e2p = exp((double)s2), e2n = exp(0.01*(double)s2);
    double den = e2p*(g_prefE[NN*2+0] - g_prefE[m*2+0]) + e2n*g_prefE[m*2+1];
    __syncthreads();
    #pragma unroll
    for (int q=0; q<2; q++){
        int d = lane + q*32;
        double Pt = g_prefP[NN*HH + d];
        double num = e2p*(Pt - g_prefP[m*HH + d]) + e2n*g_prefQ[m*HH + d];
        sH[w][d] = (float)(num/den) + g_hidden[i*HH + d];
    }
    __syncwarp();
    float partial = 0.f;
    #pragma unroll
    for (int q=0; q<2; q++){
        int o = lane + q*32;
        float acc = sFb[o];
        #pragma unroll 8
        for (int k=0; k<HH; k++) acc += sFcT[k*HH+o]*sH[w][k];
        acc = (acc >= 0.f) ? acc : 0.01f*acc;
        partial += acc*sOw[o];
    }
    #pragma unroll
    for (int off=16; off; off>>=1) partial += __shfl_down_sync(0xffffffffu, partial, off);
    if (lane == 0) out[i] = partial + outb[0];
}

extern "C" void kernel_launch(void* const* d_in, const int* in_sizes, int n_in,
                              void* d_out, int out_size)
{
    const float* x    = (const float*)d_in[0];
    const float* Wih0 = (const float*)d_in[1];
    const float* Whh0 = (const float*)d_in[2];
    const float* bih0 = (const float*)d_in[3];
    const float* bhh0 = (const float*)d_in[4];
    const float* Wih1 = (const float*)d_in[5];
    const float* Whh1 = (const float*)d_in[6];
    const float* bih1 = (const float*)d_in[7];
    const float* bhh1 = (const float*)d_in[8];
    const float* trW  = (const float*)d_in[9];
    const float* trb  = (const float*)d_in[10];
    const float* a    = (const float*)d_in[11];
    const float* fcW  = (const float*)d_in[12];
    const float* fcb  = (const float*)d_in[13];
    const float* outW = (const float*)d_in[14];
    const float* outb = (const float*)d_in[15];

    cudaFuncSetAttribute(gru_kernel,  cudaFuncAttributeMaxDynamicSharedMemorySize, SMEM_GRU);
    cudaFuncSetAttribute(sort_kernel, cudaFuncAttributeMaxDynamicSharedMemorySize, 32768);

    transpose_kernel<<<NN/32, 256>>>(x);
    gru_kernel<<<128, 512, SMEM_GRU>>>(Wih0, Whh0, bih0, bhh0, Wih1, Whh1, bih1, bhh1);
    post_kernel<<<NN/8, 512>>>(trW, trb, a);
    sort_kernel<<<1, 1024, 32768>>>();
    exp_kernel<<<NN/256, 256>>>();
    scan_kernel<<<129, 1024>>>();
    final_kernel<<<NN/8, 256>>>(fcW, fcb, outW, outb, (float*)d_out);
}

// round 14
// speedup vs baseline: 1.5740x; 1.0955x over previous
#include <cuda_runtime.h>
#include <cuda_fp16.h>
#include <math.h>

#define NN 8192
#define TT 60
#define HH 64

__device__ float g_xt[(size_t)TT*NN*8];
__device__ float g_hidden[NN*HH];
__device__ float g_s1[NN];
__device__ float g_s2[NN];
__device__ unsigned g_keys32[NN];
__device__ unsigned g_ksort[NN];
__device__ float g_s1s[NN];
__device__ int   g_perm[NN];
__device__ double g_e1[NN];
__device__ double g_e01[NN];
__device__ double g_prefP[(NN+1)*HH];
__device__ double g_prefQ[(NN+1)*HH];
__device__ double g_prefE[(NN+1)*2];

__device__ __forceinline__ float sig_f(float x){ return 1.f/(1.f+__expf(-x)); }
__device__ __forceinline__ float tanh_f(float x){ return 1.f-2.f/(__expf(2.f*x)+1.f); }
__device__ __forceinline__ unsigned f2u(float f){
    unsigned u = __float_as_uint(f);
    return (u & 0x80000000u) ? ~u : (u | 0x80000000u);
}

__device__ __forceinline__ unsigned pk2h(float lo, float hi){
    unsigned r;
    asm("{.reg .b16 l,h;\n cvt.rn.f16.f32 l, %1;\n cvt.rn.f16.f32 h, %2;\n mov.b32 %0, {l,h};}"
        : "=r"(r) : "f"(lo), "f"(hi));
    return r;
}
__device__ __forceinline__ float hfr(float v){
    float o;
    asm("{.reg .b16 t;\n cvt.rn.f16.f32 t, %1;\n cvt.f32.f16 %0, t;}" : "=f"(o) : "f"(v));
    return o;
}
__device__ __forceinline__ unsigned short h16(float v){
    unsigned short s;
    asm("{.reg .b16 t;\n cvt.rn.f16.f32 t, %1;\n mov.b16 %0, t;}" : "=h"(s) : "f"(v));
    return s;
}
__device__ __forceinline__ float2 uhf2(unsigned u){
    float2 f;
    asm("{.reg .b16 l,h;\n mov.b32 {l,h}, %2;\n cvt.f32.f16 %0, l;\n cvt.f32.f16 %1, h;}"
        : "=f"(f.x), "=f"(f.y) : "r"(u));
    return f;
}

#define MMA16(C, A, B0, B1) \
    asm("mma.sync.aligned.m16n8k16.row.col.f32.f16.f16.f32 " \
        "{%0,%1,%2,%3},{%4,%5,%6,%7},{%8,%9},{%0,%1,%2,%3};" \
        : "+f"(C[0]),"+f"(C[1]),"+f"(C[2]),"+f"(C[3]) \
        : "r"((A)[0]),"r"((A)[1]),"r"((A)[2]),"r"((A)[3]),"r"(B0),"r"(B1))

#define MMA8(C, A0, A1, B0) \
    asm("mma.sync.aligned.m16n8k8.row.col.f32.f16.f16.f32 " \
        "{%0,%1,%2,%3},{%4,%5},{%6},{%0,%1,%2,%3};" \
        : "+f"(C[0]),"+f"(C[1]),"+f"(C[2]),"+f"(C[3]) \
        : "r"(A0),"r"(A1),"r"(B0))

#define LDSM4(Q, ADDR) \
    asm volatile("ldmatrix.sync.aligned.m8n8.x4.shared.b16 {%0,%1,%2,%3},[%4];" \
        : "=r"(Q.x),"=r"(Q.y),"=r"(Q.z),"=r"(Q.w) : "r"(ADDR))

#define LDSM4A(A, ADDR) \
    asm volatile("ldmatrix.sync.aligned.m8n8.x4.shared.b16 {%0,%1,%2,%3},[%4];" \
        : "=r"((A)[0]),"=r"((A)[1]),"=r"((A)[2]),"=r"((A)[3]) : "r"(ADDR) : "memory")

#define STS32(ADDR, V) \
    asm volatile("st.shared.u32 [%0], %1;" :: "r"(ADDR), "r"(V) : "memory")

// smem byte offsets (S0 and S1 both double-buffered: 2 x 9216 each region)
#define XWHI 0
#define W0HI 3072
#define WI1HI 30720
#define WH1HI 58368
#define BIASO 86016
#define S0HI 88064
#define S0LO 106496
#define S1HI 124928
#define S1LO 143360
#define SMEM_GRU 161792

__device__ __forceinline__ unsigned smem_u32(const void* p){
    unsigned a; asm("{ .reg .u64 t; cvta.to.shared.u64 t, %1; cvt.u32.u64 %0, t; }" : "=r"(a) : "l"(p));
    return a;
}

#define GATE_EPI2(Cr,Cz,Ci,Chn, BOFF, n0_, AHI, ALO, i0_, SH_, SL_) do{ \
    float2 _br = *(const float2*)(sbias + (BOFF) + (n0_) + 2*c); \
    float2 _bz = *(const float2*)(sbias + (BOFF) + 64 + (n0_) + 2*c); \
    float2 _bi = *(const float2*)(sbias + (BOFF) + 128 + (n0_) + 2*c); \
    float2 _bh = *(const float2*)(sbias + (BOFF) + 192 + (n0_) + 2*c); \
    float2 _p0 = uhf2((AHI)[i0_]),   _q0 = uhf2((ALO)[i0_]); \
    float2 _p1 = uhf2((AHI)[i0_+1]), _q1 = uhf2((ALO)[i0_+1]); \
    float _hp0=_p0.x+_q0.x, _hp1=_p0.y+_q0.y, _hp2=_p1.x+_q1.x, _hp3=_p1.y+_q1.y; \
    float _r0=sig_f(Cr[0]+_br.x), _r1=sig_f(Cr[1]+_br.y), _r2=sig_f(Cr[2]+_br.x), _r3=sig_f(Cr[3]+_br.y); \
    float _z0=sig_f(Cz[0]+_bz.x), _z1=sig_f(Cz[1]+_bz.y), _z2=sig_f(Cz[2]+_bz.x), _z3=sig_f(Cz[3]+_bz.y); \
    float _n0=tanh_f(Ci[0]+_bi.x+_r0*(Chn[0]+_bh.x)); \
    float _n1=tanh_f(Ci[1]+_bi.y+_r1*(Chn[1]+_bh.y)); \
    float _n2=tanh_f(Ci[2]+_bi.x+_r2*(Chn[2]+_bh.x)); \
    float _n3=tanh_f(Ci[3]+_bi.y+_r3*(Chn[3]+_bh.y)); \
    float _h0=_n0+_z0*(_hp0-_n0), _h1=_n1+_z1*(_hp1-_n1); \
    float _h2=_n2+_z2*(_hp2-_n2), _h3=_n3+_z3*(_hp3-_n3); \
    STS32((SH_) + (n0_)*2,        pk2h(_h0,_h1)); \
    STS32((SH_) + (n0_)*2 + 1152, pk2h(_h2,_h3)); \
    STS32((SL_) + (n0_)*2,        pk2h(_h0-hfr(_h0), _h1-hfr(_h1))); \
    STS32((SL_) + (n0_)*2 + 1152, pk2h(_h2-hfr(_h2), _h3-hfr(_h3))); \
}while(0)

// L0 tile: hi-only MMA path (12 MMA16 + 3 MMA8); lo kept for epilogue only
#define L0_TILE(t8, XH0,XH1) do{ \
    const int n0 = (t8)*8; \
    float Cr[4]={0,0,0,0}, Cz[4]={0,0,0,0}, Ci[4]={0,0,0,0}, Chn[4]={0,0,0,0}; \
    uint4 qx; LDSM4(qx, a_x + n0*16); \
    MMA8(Cr,XH0,XH1,qx.x); MMA8(Cz,XH0,XH1,qx.y); MMA8(Ci,XH0,XH1,qx.z); \
    _Pragma("unroll") \
    for (int kp=0; kp<2; kp++){ \
        uint4 qr, qz, qn; \
        LDSM4(qr, a_w0 + n0*144 + kp*64); \
        LDSM4(qz, a_w0 + 9216 + n0*144 + kp*64); \
        LDSM4(qn, a_w0 + 18432 + n0*144 + kp*64); \
        const int k0 = 2*kp; \
        MMA16(Cr, a0h[k0], qr.x, qr.y); MMA16(Cz, a0h[k0], qz.x, qz.y); MMA16(Chn, a0h[k0], qn.x, qn.y); \
        MMA16(Cr, a0h[k0+1], qr.z, qr.w); MMA16(Cz, a0h[k0+1], qz.z, qz.w); MMA16(Chn, a0h[k0+1], qn.z, qn.w); \
    } \
    const int kt0 = (t8)>>1, i0 = ((t8)&1)*2; \
    GATE_EPI2(Cr,Cz,Ci,Chn, 0, n0, a0h[kt0], a0l[kt0], i0, st0h, st0l); \
}while(0)

// L1 tile: hi-only MMA path (24 MMA16); a1l kept for epilogue only
#define L1_TILE(t8) do{ \
    const int n0 = (t8)*8; \
    float Cri[4]={0,0,0,0}, Crh[4]={0,0,0,0}, Czi[4]={0,0,0,0}, Czh[4]={0,0,0,0}; \
    float Cii[4]={0,0,0,0}, Chn[4]={0,0,0,0}; \
    _Pragma("unroll") \
    for (int kp=0; kp<2; kp++){ \
        uint4 q0,q1,q2,q3,q4,q5; \
        LDSM4(q0, a_i1 + n0*144 + kp*64); \
        LDSM4(q1, a_h1 + n0*144 + kp*64); \
        LDSM4(q2, a_i1 + 9216 + n0*144 + kp*64); \
        LDSM4(q3, a_h1 + 9216 + n0*144 + kp*64); \
        LDSM4(q4, a_i1 + 18432 + n0*144 + kp*64); \
        LDSM4(q5, a_h1 + 18432 + n0*144 + kp*64); \
        const int k0 = 2*kp; \
        MMA16(Cri, yh[k0], q0.x, q0.y); MMA16(Crh, a1h[k0], q1.x, q1.y); \
        MMA16(Czi, yh[k0], q2.x, q2.y); MMA16(Czh, a1h[k0], q3.x, q3.y); \
        MMA16(Cii, yh[k0], q4.x, q4.y); MMA16(Chn, a1h[k0], q5.x, q5.y); \
        MMA16(Cri, yh[k0+1], q0.z, q0.w); MMA16(Crh, a1h[k0+1], q1.z, q1.w); \
        MMA16(Czi, yh[k0+1], q2.z, q2.w); MMA16(Czh, a1h[k0+1], q3.z, q3.w); \
        MMA16(Cii, yh[k0+1], q4.z, q4.w); MMA16(Chn, a1h[k0+1], q5.z, q5.w); \
    } \
    float Cr[4], Cz[4]; \
    _Pragma("unroll") \
    for (int i=0;i<4;i++){ Cr[i]=Cri[i]+Crh[i]; Cz[i]=Czi[i]+Czh[i]; } \
    const int kt0 = (t8)>>1, i0 = ((t8)&1)*2; \
    GATE_EPI2(Cr,Cz,Cii,Chn, 256, n0, a1h[kt0], a1l[kt0], i0, st1h, st1l); \
}while(0)

__global__ __launch_bounds__(256) void transpose_kernel(const float* __restrict__ x){
    __shared__ float sx[32*360];
    int nb = blockIdx.x*32, tid = threadIdx.x;
    for (int idx=tid; idx<32*360; idx+=256) sx[idx] = x[(size_t)nb*360 + idx];
    __syncthreads();
    int n = tid>>3, d = tid&7;
    float* op = g_xt + ((size_t)(nb+n))*8 + d;
    #pragma unroll 4
    for (int t=0; t<TT; t++)
        op[(size_t)t*NN*8] = (d<6) ? sx[n*360 + d*60 + t] : 0.f;
}

__global__ __launch_bounds__(512,1) void gru_kernel(
    const float* __restrict__ Wih0, const float* __restrict__ Whh0,
    const float* __restrict__ bih0, const float* __restrict__ bhh0,
    const float* __restrict__ Wih1, const float* __restrict__ Whh1,
    const float* __restrict__ bih1, const float* __restrict__ bhh1)
{
    extern __shared__ char sm[];
    const int tid = threadIdx.x;
    unsigned short* xw = (unsigned short*)(sm + XWHI);
    for (int i=tid; i<1536; i+=512) xw[i]=0;
    for (int i=tid; i<1152; i+=512){
        int n = i/6, d = i - n*6;
        xw[n*8+d] = h16(Wih0[i]);
    }
    {
        unsigned short* w0 = (unsigned short*)(sm + W0HI);
        unsigned short* i1 = (unsigned short*)(sm + WI1HI);
        unsigned short* h1 = (unsigned short*)(sm + WH1HI);
        for (int i=tid; i<12288; i+=512){
            int n = i>>6, k = i&63, o = n*72+k;
            w0[o] = h16(Whh0[i]);
            i1[o] = h16(Wih1[i]);
            h1[o] = h16(Whh1[i]);
        }
    }
    for (int i=tid; i<73728/4; i+=512) ((unsigned*)(sm + S0HI))[i] = 0u;
    float* sbias = (float*)(sm + BIASO);
    if (tid < 64){
        int j = tid;
        sbias[j]     = bih0[j]    + bhh0[j];
        sbias[64+j]  = bih0[64+j] + bhh0[64+j];
        sbias[128+j] = bih0[128+j];
        sbias[192+j] = bhh0[128+j];
        sbias[256+j] = bih1[j]    + bhh1[j];
        sbias[320+j] = bih1[64+j] + bhh1[64+j];
        sbias[384+j] = bih1[128+j];
        sbias[448+j] = bhh1[128+j];
    }
    __syncthreads();

    const int lane = tid & 31, warp = tid >> 5;
    const int grp = warp & 3;            // SMSP id == group
    const int role = warp >> 2;          // 0,1: L0 halves; 2,3: L1 halves
    const int half = role & 1;
    const int rquad = lane >> 2, c = lane & 3;
    const int row0 = blockIdx.x*64 + grp*16 + rquad;
    const unsigned smb = smem_u32(sm);
    const int sub = lane >> 3, r8 = lane & 7;
    const unsigned soff = r8*144 + sub*16;
    const unsigned a_w0 = smb + W0HI  + soff;
    const unsigned a_i1 = smb + WI1HI + soff;
    const unsigned a_h1 = smb + WH1HI + soff;
    const unsigned xgrow = (sub==0) ? 0u : (sub==1 ? 64u : 128u);
    const unsigned a_x = smb + XWHI + (xgrow + r8)*16;

    const unsigned lsl = (lane & 15)*144 + (lane >> 4)*16;
    const unsigned stb = grp*2304 + rquad*144 + 4*c;

    #pragma unroll 1
    for (int it=0; it<=TT; it++){
        if (role < 2 && it < TT){
            const int t = it;
            const unsigned rd = (unsigned)(((t+1)&1)*9216);
            const unsigned wr = (unsigned)((t&1)*9216);
            unsigned a0h[4][4], a0l[4][4];
            #pragma unroll
            for (int kt=0;kt<4;kt++){
                LDSM4A(a0h[kt], smb + S0HI + rd + grp*2304 + lsl + kt*32);
                LDSM4A(a0l[kt], smb + S0LO + rd + grp*2304 + lsl + kt*32);
            }
            const float* _xp = g_xt + ((size_t)t*NN + row0)*8 + 2*c;
            float2 _x0 = *(const float2*)_xp;
            float2 _x1 = *(const float2*)(_xp + 64);
            unsigned xh0 = pk2h(_x0.x, _x0.y);
            unsigned xh1 = pk2h(_x1.x, _x1.y);
            const unsigned st0h = smb + S0HI + wr + stb;
            const unsigned st0l = smb + S0LO + wr + stb;
            if (!half){
                #pragma unroll
                for (int t8=0; t8<4; t8++) L0_TILE(t8, xh0,xh1);
            } else {
                #pragma unroll
                for (int t8=4; t8<8; t8++) L0_TILE(t8, xh0,xh1);
            }
        }
        if (role >= 2 && it >= 1){
            const int t = it - 1;
            const unsigned rd0 = (unsigned)((t&1)*9216);        // h0(t), written by L0 last iter
            const unsigned rd1 = (unsigned)(((t+1)&1)*9216);    // h1(t-1)
            const unsigned wr1 = (unsigned)((t&1)*9216);        // h1(t)
            unsigned yh[4][4], a1h[4][4], a1l[4][4];
            #pragma unroll
            for (int kt=0;kt<4;kt++){
                LDSM4A(yh[kt],  smb + S0HI + rd0 + grp*2304 + lsl + kt*32);
                LDSM4A(a1h[kt], smb + S1HI + rd1 + grp*2304 + lsl + kt*32);
                LDSM4A(a1l[kt], smb + S1LO + rd1 + grp*2304 + lsl + kt*32);
            }
            const unsigned st1h = smb + S1HI + wr1 + stb;
            const unsigned st1l = smb + S1LO + wr1 + stb;
            if (!half){
                #pragma unroll
                for (int t8=0; t8<4; t8++) L1_TILE(t8);
            } else {
                #pragma unroll
                for (int t8=4; t8<8; t8++) L1_TILE(t8);
            }
        }
        __syncthreads();
    }

    // final h1 = buffer of t=59 -> (59&1)=1
    if (role == 3){
        const char* p1h = sm + S1HI + 9216 + grp*2304;
        const char* p1l = sm + S1LO + 9216 + grp*2304;
        for (int i=lane; i<16*32; i+=32){
            int row = i>>5, cp = i&31;
            unsigned vh = *(const unsigned*)(p1h + row*144 + cp*4);
            unsigned vl = *(const unsigned*)(p1l + row*144 + cp*4);
            float2 a = uhf2(vh), b = uhf2(vl);
            float2 v; v.x = a.x + b.x; v.y = a.y + b.y;
            *(float2*)(g_hidden + (size_t)(blockIdx.x*64 + grp*16 + row)*64 + cp*2) = v;
        }
    }
}

__global__ __launch_bounds__(512) void post_kernel(
    const float* __restrict__ trW, const float* __restrict__ trb, const float* __restrict__ a)
{
    __shared__ float sWt[HH*HH];
    __shared__ float sh[8*HH];
    __shared__ float sa[2*HH];
    __shared__ float sred[16][2];
    int tid = threadIdx.x;
    for (int idx=tid; idx<HH*HH; idx+=512){ int o=idx>>6, k=idx&63; sWt[k*HH+o]=trW[idx]; }
    if (tid < 2*HH) sa[tid] = a[tid];
    int lr = tid>>6, j = tid&63;
    int i = blockIdx.x*8 + lr;
    sh[lr*HH+j] = g_hidden[i*HH+j];
    __syncthreads();
    float acc = trb[j];
    #pragma unroll 8
    for (int k=0; k<HH; k++) acc += sWt[k*HH+j]*sh[lr*HH+k];
    float p1 = acc*sa[j], p2 = acc*sa[HH+j];
    #pragma unroll
    for (int off=16; off; off>>=1){
        p1 += __shfl_down_sync(0xffffffffu, p1, off);
        p2 += __shfl_down_sync(0xffffffffu, p2, off);
    }
    int wid = tid>>5;
    if ((tid&31)==0){ sred[wid][0]=p1; sred[wid][1]=p2; }
    __syncthreads();
    if (tid < 8){
        float s1 = sred[2*tid][0] + sred[2*tid+1][0];
        float s2 = sred[2*tid][1] + sred[2*tid+1][1];
        int n = blockIdx.x*8 + tid;
        g_s1[n] = s1; g_s2[n] = s2;
        unsigned u = f2u(s1);
        g_keys32[n] = ((u >> 13) << 13) | (unsigned)n;
    }
}

__global__ __launch_bounds__(1024) void sort_kernel(){
    extern __shared__ unsigned sk32[];
    int tid = threadIdx.x;
    for (int i=tid; i<NN; i+=1024) sk32[i] = g_keys32[i];
    __syncthreads();
    for (int k=2; k<=NN; k<<=1){
        for (int j=k>>1; j>0; j>>=1){
            for (int i=tid; i<NN; i+=1024){
                int ixj = i^j;
                if (ixj > i){
                    unsigned va = sk32[i], vb = sk32[ixj];
                    bool up = ((i & k) == 0);
                    if ((va > vb) == up){ sk32[i]=vb; sk32[ixj]=va; }
                }
            }
            __syncthreads();
        }
    }
    for (int r=tid; r<NN; r+=1024){
        unsigned key = sk32[r];
        int idx = (int)(key & 8191u);
        g_perm[r]  = idx;
        g_s1s[r]   = g_s1[idx];
        g_ksort[r] = key;
    }
}

__global__ __launch_bounds__(256) void exp_kernel(){
    int i = blockIdx.x*256 + threadIdx.x;
    double v = (double)g_s1s[i];
    g_e1[i]  = exp(v);
    g_e01[i] = exp(0.01*v);
}

__global__ __launch_bounds__(1024) void scan_kernel(){
    __shared__ double ssum[1024];
    int c = blockIdx.x, tid = threadIdx.x;
    int nscans = (c == 128) ? 2 : 1;
    for (int s=0; s<nscans; s++){
        double local[8], ts = 0.0;
        #pragma unroll
        for (int e=0; e<8; e++){
            int r = tid*8 + e;
            double w;
            if (c < 64)       w = g_e1[r]  * (double)g_hidden[g_perm[r]*HH + c];
            else if (c < 128) w = g_e01[r] * (double)g_hidden[g_perm[r]*HH + (c-64)];
            else              w = (s == 0) ? g_e1[r] : g_e01[r];
            local[e] = w; ts += w;
        }
        ssum[tid] = ts; __syncthreads();
        for (int off=1; off<1024; off<<=1){
            double v = ssum[tid];
            if (tid >= off) v += ssum[tid-off];
            __syncthreads(); ssum[tid] = v; __syncthreads();
        }
        double run = tid ? ssum[tid-1] : 0.0;
        #pragma unroll
        for (int e=0; e<8; e++){
            int r = tid*8 + e;
            if (c < 64)       g_prefP[r*HH + c]      = run;
            else if (c < 128) g_prefQ[r*HH + (c-64)] = run;
            else              g_prefE[r*2 + s]        = run;
            run += local[e];
        }
        if (tid == 1023){
            double tot = ssum[1023];
            if (c < 64)       g_prefP[NN*HH + c]      = tot;
            else if (c < 128) g_prefQ[NN*HH + (c-64)] = tot;
            else              g_prefE[NN*2 + s]        = tot;
        }
        __syncthreads();
    }
}

__global__ __launch_bounds__(256) void final_kernel(
    const float* __restrict__ fcW, const float* __restrict__ fcb,
    const float* __restrict__ outW, const float* __restrict__ outb,
    float* __restrict__ out)
{
    __shared__ float sFcT[HH*HH];
    __shared__ float sOw[HH], sFb[HH];
    __shared__ float sH[8][HH];
    int tid = threadIdx.x;
    for (int idx=tid; idx<HH*HH; idx+=256){ int o=idx>>6, k=idx&63; sFcT[k*HH+o]=fcW[idx]; }
    if (tid < HH){ sOw[tid]=outW[tid]; sFb[tid]=fcb[tid]; }
    int w = tid>>5, lane = tid&31;
    int i = blockIdx.x*8 + w;
    float s2 = g_s2[i];
    unsigned thrkey = (f2u(-s2) >> 13) << 13;
    int lo = 0, hi = NN;
    while (lo < hi){ int mid = (lo+hi)>>1; if (g_ksort[mid] < thrkey) lo = mid+1; else hi = mid; }
    int m = lo;
    double e2p = exp((double)s2), e2n = exp(0.01*(double)s2);
    double den = e2p*(g_prefE[NN*2+0] - g_prefE[m*2+0]) + e2n*g_prefE[m*2+1];
    __syncthreads();
    #pragma unroll
    for (int q=0; q<2; q++){
        int d = lane + q*32;
        double Pt = g_prefP[NN*HH + d];
        double num = e2p*(Pt - g_prefP[m*HH + d]) + e2n*g_prefQ[m*HH + d];
        sH[w][d] = (float)(num/den) + g_hidden[i*HH + d];
    }
    __syncwarp();
    float partial = 0.f;
    #pragma unroll
    for (int q=0; q<2; q++){
        int o = lane + q*32;
        float acc = sFb[o];
        #pragma unroll 8
        for (int k=0; k<HH; k++) acc += sFcT[k*HH+o]*sH[w][k];
        acc = (acc >= 0.f) ? acc : 0.01f*acc;
        partial += acc*sOw[o];
    }
    #pragma unroll
    for (int off=16; off; off>>=1) partial += __shfl_down_sync(0xffffffffu, partial, off);
    if (lane == 0) out[i] = partial + outb[0];
}

extern "C" void kernel_launch(void* const* d_in, const int* in_sizes, int n_in,
                              void* d_out, int out_size)
{
    const float* x    = (const float*)d_in[0];
    const float* Wih0 = (const float*)d_in[1];
    const float* Whh0 = (const float*)d_in[2];
    const float* bih0 = (const float*)d_in[3];
    const float* bhh0 = (const float*)d_in[4];
    const float* Wih1 = (const float*)d_in[5];
    const float* Whh1 = (const float*)d_in[6];
    const float* bih1 = (const float*)d_in[7];
    const float* bhh1 = (const float*)d_in[8];
    const float* trW  = (const float*)d_in[9];
    const float* trb  = (const float*)d_in[10];
    const float* a    = (const float*)d_in[11];
    const float* fcW  = (const float*)d_in[12];
    const float* fcb  = (const float*)d_in[13];
    const float* outW = (const float*)d_in[14];
    const float* outb = (const float*)d_in[15];

    cudaFuncSetAttribute(gru_kernel,  cudaFuncAttributeMaxDynamicSharedMemorySize, SMEM_GRU);
    cudaFuncSetAttribute(sort_kernel, cudaFuncAttributeMaxDynamicSharedMemorySize, 32768);

    transpose_kernel<<<NN/32, 256>>>(x);
    gru_kernel<<<128, 512, SMEM_GRU>>>(Wih0, Whh0, bih0, bhh0, Wih1, Whh1, bih1, bhh1);
    post_kernel<<<NN/8, 512>>>(trW, trb, a);
    sort_kernel<<<1, 1024, 32768>>>();
    exp_kernel<<<NN/256, 256>>>();
    scan_kernel<<<129, 1024>>>();
    final_kernel<<<NN/8, 256>>>(fcW, fcb, outW, outb, (float*)d_out);
}

// round 15
// speedup vs baseline: 2.6057x; 1.6554x over previous
#include <cuda_runtime.h>
#include <cuda_fp16.h>
#include <math.h>

#define NN 8192
#define TT 60
#define HH 64

__device__ float g_xt[(size_t)TT*NN*8];
__device__ float g_hidden[NN*HH];
__device__ float g_s1[NN];
__device__ float g_s2[NN];
__device__ unsigned g_keys32[NN];
__device__ unsigned g_ksort[NN];
__device__ float g_s1s[NN];
__device__ int   g_perm[NN];
__device__ double g_e1[NN];
__device__ double g_e01[NN];
__device__ double g_prefP[(NN+1)*HH];
__device__ double g_prefQ[(NN+1)*HH];
__device__ double g_prefE[(NN+1)*2];

__device__ __forceinline__ float tanh_a(float x){
    float t; asm("tanh.approx.f32 %0, %1;" : "=f"(t) : "f"(x)); return t;
}
__device__ __forceinline__ float sig_a(float x){
    float t; asm("tanh.approx.f32 %0, %1;" : "=f"(t) : "f"(0.5f*x));
    return fmaf(t, 0.5f, 0.5f);
}
__device__ __forceinline__ float sig_f(float x){ return 1.f/(1.f+__expf(-x)); }
__device__ __forceinline__ unsigned f2u(float f){
    unsigned u = __float_as_uint(f);
    return (u & 0x80000000u) ? ~u : (u | 0x80000000u);
}

__device__ __forceinline__ unsigned pk2h(float lo, float hi){
    unsigned r;
    asm("{.reg .b16 l,h;\n cvt.rn.f16.f32 l, %1;\n cvt.rn.f16.f32 h, %2;\n mov.b32 %0, {l,h};}"
        : "=r"(r) : "f"(lo), "f"(hi));
    return r;
}
__device__ __forceinline__ unsigned short h16(float v){
    unsigned short s;
    asm("{.reg .b16 t;\n cvt.rn.f16.f32 t, %1;\n mov.b16 %0, t;}" : "=h"(s) : "f"(v));
    return s;
}

#define MMA16(C, A, B0, B1) \
    asm("mma.sync.aligned.m16n8k16.row.col.f32.f16.f16.f32 " \
        "{%0,%1,%2,%3},{%4,%5,%6,%7},{%8,%9},{%0,%1,%2,%3};" \
        : "+f"(C[0]),"+f"(C[1]),"+f"(C[2]),"+f"(C[3]) \
        : "r"((A)[0]),"r"((A)[1]),"r"((A)[2]),"r"((A)[3]),"r"(B0),"r"(B1))

#define MMA8(C, A0, A1, B0) \
    asm("mma.sync.aligned.m16n8k8.row.col.f32.f16.f16.f32 " \
        "{%0,%1,%2,%3},{%4,%5},{%6},{%0,%1,%2,%3};" \
        : "+f"(C[0]),"+f"(C[1]),"+f"(C[2]),"+f"(C[3]) \
        : "r"(A0),"r"(A1),"r"(B0))

#define LDSM4(Q, ADDR) \
    asm volatile("ldmatrix.sync.aligned.m8n8.x4.shared.b16 {%0,%1,%2,%3},[%4];" \
        : "=r"(Q.x),"=r"(Q.y),"=r"(Q.z),"=r"(Q.w) : "r"(ADDR))

#define LDSM4A(A, ADDR) \
    asm volatile("ldmatrix.sync.aligned.m8n8.x4.shared.b16 {%0,%1,%2,%3},[%4];" \
        : "=r"((A)[0]),"=r"((A)[1]),"=r"((A)[2]),"=r"((A)[3]) : "r"(ADDR) : "memory")

#define STS32(ADDR, V) \
    asm volatile("st.shared.u32 [%0], %1;" :: "r"(ADDR), "r"(V) : "memory")

// smem byte offsets (hi-only state, double-buffered)
#define XWHI 0
#define W0HI 3072
#define WI1HI 30720
#define WH1HI 58368
#define BIASO 86016
#define S0HI 88064
#define S1HI 106496
#define SMEM_GRU 124928

__device__ __forceinline__ unsigned smem_u32(const void* p){
    unsigned a; asm("{ .reg .u64 t; cvta.to.shared.u64 t, %1; cvt.u32.u64 %0, t; }" : "=r"(a) : "l"(p));
    return a;
}

// epilogue: gate accums + register h_prev -> new h (fp32 regs) + hi f16 to smem
#define GATE_EPIR(Cr,Cz,Ci,Chn, BOFF, n0_, HP, SH_) do{ \
    float2 _br = *(const float2*)(sbias + (BOFF) + (n0_) + 2*c); \
    float2 _bz = *(const float2*)(sbias + (BOFF) + 64 + (n0_) + 2*c); \
    float2 _bi = *(const float2*)(sbias + (BOFF) + 128 + (n0_) + 2*c); \
    float2 _bh = *(const float2*)(sbias + (BOFF) + 192 + (n0_) + 2*c); \
    float _r0=sig_a(Cr[0]+_br.x), _r1=sig_a(Cr[1]+_br.y), _r2=sig_a(Cr[2]+_br.x), _r3=sig_a(Cr[3]+_br.y); \
    float _z0=sig_a(Cz[0]+_bz.x), _z1=sig_a(Cz[1]+_bz.y), _z2=sig_a(Cz[2]+_bz.x), _z3=sig_a(Cz[3]+_bz.y); \
    float _n0=tanh_a(Ci[0]+_bi.x+_r0*(Chn[0]+_bh.x)); \
    float _n1=tanh_a(Ci[1]+_bi.y+_r1*(Chn[1]+_bh.y)); \
    float _n2=tanh_a(Ci[2]+_bi.x+_r2*(Chn[2]+_bh.x)); \
    float _n3=tanh_a(Ci[3]+_bi.y+_r3*(Chn[3]+_bh.y)); \
    float _h0=_n0+_z0*((HP)[0]-_n0), _h1=_n1+_z1*((HP)[1]-_n1); \
    float _h2=_n2+_z2*((HP)[2]-_n2), _h3=_n3+_z3*((HP)[3]-_n3); \
    (HP)[0]=_h0; (HP)[1]=_h1; (HP)[2]=_h2; (HP)[3]=_h3; \
    STS32((SH_) + (n0_)*2,        pk2h(_h0,_h1)); \
    STS32((SH_) + (n0_)*2 + 1152, pk2h(_h2,_h3)); \
}while(0)

#define L0_TILE(t8, XH0,XH1) do{ \
    const int n0 = (t8)*8; \
    float Cr[4]={0,0,0,0}, Cz[4]={0,0,0,0}, Ci[4]={0,0,0,0}, Chn[4]={0,0,0,0}; \
    uint4 qx; LDSM4(qx, a_x + n0*16); \
    MMA8(Cr,XH0,XH1,qx.x); MMA8(Cz,XH0,XH1,qx.y); MMA8(Ci,XH0,XH1,qx.z); \
    _Pragma("unroll") \
    for (int kp=0; kp<2; kp++){ \
        uint4 qr, qz, qn; \
        LDSM4(qr, a_w0 + n0*144 + kp*64); \
        LDSM4(qz, a_w0 + 9216 + n0*144 + kp*64); \
        LDSM4(qn, a_w0 + 18432 + n0*144 + kp*64); \
        const int k0 = 2*kp; \
        MMA16(Cr, a0h[k0], qr.x, qr.y); MMA16(Cz, a0h[k0], qz.x, qz.y); MMA16(Chn, a0h[k0], qn.x, qn.y); \
        MMA16(Cr, a0h[k0+1], qr.z, qr.w); MMA16(Cz, a0h[k0+1], qz.z, qz.w); MMA16(Chn, a0h[k0+1], qn.z, qn.w); \
    } \
    GATE_EPIR(Cr,Cz,Ci,Chn, 0, n0, hp[(t8)&3], st0h); \
}while(0)

#define L1_TILE(t8) do{ \
    const int n0 = (t8)*8; \
    float Cri[4]={0,0,0,0}, Crh[4]={0,0,0,0}, Czi[4]={0,0,0,0}, Czh[4]={0,0,0,0}; \
    float Cii[4]={0,0,0,0}, Chn[4]={0,0,0,0}; \
    _Pragma("unroll") \
    for (int kp=0; kp<2; kp++){ \
        uint4 q0,q1,q2,q3,q4,q5; \
        LDSM4(q0, a_i1 + n0*144 + kp*64); \
        LDSM4(q1, a_h1 + n0*144 + kp*64); \
        LDSM4(q2, a_i1 + 9216 + n0*144 + kp*64); \
        LDSM4(q3, a_h1 + 9216 + n0*144 + kp*64); \
        LDSM4(q4, a_i1 + 18432 + n0*144 + kp*64); \
        LDSM4(q5, a_h1 + 18432 + n0*144 + kp*64); \
        const int k0 = 2*kp; \
        MMA16(Cri, yh[k0], q0.x, q0.y); MMA16(Crh, a1h[k0], q1.x, q1.y); \
        MMA16(Czi, yh[k0], q2.x, q2.y); MMA16(Czh, a1h[k0], q3.x, q3.y); \
        MMA16(Cii, yh[k0], q4.x, q4.y); MMA16(Chn, a1h[k0], q5.x, q5.y); \
        MMA16(Cri, yh[k0+1], q0.z, q0.w); MMA16(Crh, a1h[k0+1], q1.z, q1.w); \
        MMA16(Czi, yh[k0+1], q2.z, q2.w); MMA16(Czh, a1h[k0+1], q3.z, q3.w); \
        MMA16(Cii, yh[k0+1], q4.z, q4.w); MMA16(Chn, a1h[k0+1], q5.z, q5.w); \
    } \
    float Cr[4], Cz[4]; \
    _Pragma("unroll") \
    for (int i=0;i<4;i++){ Cr[i]=Cri[i]+Crh[i]; Cz[i]=Czi[i]+Czh[i]; } \
    GATE_EPIR(Cr,Cz,Cii,Chn, 256, n0, hp[(t8)&3], st1h); \
}while(0)

__global__ __launch_bounds__(256) void transpose_kernel(const float* __restrict__ x){
    __shared__ float sx[32*360];
    int nb = blockIdx.x*32, tid = threadIdx.x;
    for (int idx=tid; idx<32*360; idx+=256) sx[idx] = x[(size_t)nb*360 + idx];
    __syncthreads();
    int n = tid>>3, d = tid&7;
    float* op = g_xt + ((size_t)(nb+n))*8 + d;
    #pragma unroll 4
    for (int t=0; t<TT; t++)
        op[(size_t)t*NN*8] = (d<6) ? sx[n*360 + d*60 + t] : 0.f;
}

__global__ __launch_bounds__(512,1) void gru_kernel(
    const float* __restrict__ Wih0, const float* __restrict__ Whh0,
    const float* __restrict__ bih0, const float* __restrict__ bhh0,
    const float* __restrict__ Wih1, const float* __restrict__ Whh1,
    const float* __restrict__ bih1, const float* __restrict__ bhh1)
{
    extern __shared__ char sm[];
    const int tid = threadIdx.x;
    unsigned short* xw = (unsigned short*)(sm + XWHI);
    for (int i=tid; i<1536; i+=512) xw[i]=0;
    for (int i=tid; i<1152; i+=512){
        int n = i/6, d = i - n*6;
        xw[n*8+d] = h16(Wih0[i]);
    }
    {
        unsigned short* w0 = (unsigned short*)(sm + W0HI);
        unsigned short* i1 = (unsigned short*)(sm + WI1HI);
        unsigned short* h1 = (unsigned short*)(sm + WH1HI);
        for (int i=tid; i<12288; i+=512){
            int n = i>>6, k = i&63, o = n*72+k;
            w0[o] = h16(Whh0[i]);
            i1[o] = h16(Wih1[i]);
            h1[o] = h16(Whh1[i]);
        }
    }
    for (int i=tid; i<36864/4; i+=512) ((unsigned*)(sm + S0HI))[i] = 0u;
    float* sbias = (float*)(sm + BIASO);
    if (tid < 64){
        int j = tid;
        sbias[j]     = bih0[j]    + bhh0[j];
        sbias[64+j]  = bih0[64+j] + bhh0[64+j];
        sbias[128+j] = bih0[128+j];
        sbias[192+j] = bhh0[128+j];
        sbias[256+j] = bih1[j]    + bhh1[j];
        sbias[320+j] = bih1[64+j] + bhh1[64+j];
        sbias[384+j] = bih1[128+j];
        sbias[448+j] = bhh1[128+j];
    }
    __syncthreads();

    const int lane = tid & 31, warp = tid >> 5;
    const int grp = warp & 3;            // SMSP id == group
    const int role = warp >> 2;          // 0,1: L0 halves; 2,3: L1 halves
    const int half = role & 1;
    const int rquad = lane >> 2, c = lane & 3;
    const int row0 = blockIdx.x*64 + grp*16 + rquad;
    const unsigned smb = smem_u32(sm);
    const int sub = lane >> 3, r8 = lane & 7;
    const unsigned soff = r8*144 + sub*16;
    const unsigned a_w0 = smb + W0HI  + soff;
    const unsigned a_i1 = smb + WI1HI + soff;
    const unsigned a_h1 = smb + WH1HI + soff;
    const unsigned xgrow = (sub==0) ? 0u : (sub==1 ? 64u : 128u);
    const unsigned a_x = smb + XWHI + (xgrow + r8)*16;

    const unsigned lsl = (lane & 15)*144 + (lane >> 4)*16;
    const unsigned stb = grp*2304 + rquad*144 + 4*c;

    float hp[4][4];
    #pragma unroll
    for (int a=0;a<4;a++)
        #pragma unroll
        for (int b=0;b<4;b++) hp[a][b] = 0.f;

    #pragma unroll 1
    for (int it=0; it<=TT; it++){
        if (role < 2 && it < TT){
            const int t = it;
            const unsigned rd = (unsigned)(((t+1)&1)*9216);
            const unsigned wr = (unsigned)((t&1)*9216);
            unsigned a0h[4][4];
            #pragma unroll
            for (int kt=0;kt<4;kt++)
                LDSM4A(a0h[kt], smb + S0HI + rd + grp*2304 + lsl + kt*32);
            const float* _xp = g_xt + ((size_t)t*NN + row0)*8 + 2*c;
            float2 _x0 = *(const float2*)_xp;
            float2 _x1 = *(const float2*)(_xp + 64);
            unsigned xh0 = pk2h(_x0.x, _x0.y);
            unsigned xh1 = pk2h(_x1.x, _x1.y);
            const unsigned st0h = smb + S0HI + wr + stb;
            if (!half){
                #pragma unroll
                for (int t8=0; t8<4; t8++) L0_TILE(t8, xh0,xh1);
            } else {
                #pragma unroll
                for (int t8=4; t8<8; t8++) L0_TILE(t8, xh0,xh1);
            }
        }
        if (role >= 2 && it >= 1){
            const int t = it - 1;
            const unsigned rd0 = (unsigned)((t&1)*9216);        // h0(t)
            const unsigned rd1 = (unsigned)(((t+1)&1)*9216);    // h1(t-1)
            const unsigned wr1 = (unsigned)((t&1)*9216);        // h1(t)
            unsigned yh[4][4], a1h[4][4];
            #pragma unroll
            for (int kt=0;kt<4;kt++){
                LDSM4A(yh[kt],  smb + S0HI + rd0 + grp*2304 + lsl + kt*32);
                LDSM4A(a1h[kt], smb + S1HI + rd1 + grp*2304 + lsl + kt*32);
            }
            const unsigned st1h = smb + S1HI + wr1 + stb;
            if (!half){
                #pragma unroll
                for (int t8=0; t8<4; t8++) L1_TILE(t8);
            } else {
                #pragma unroll
                for (int t8=4; t8<8; t8++) L1_TILE(t8);
            }
        }
        __syncthreads();
    }

    // final h1 lives in L1 warps' registers (exact fp32)
    if (role >= 2){
        #pragma unroll
        for (int ti=0; ti<4; ti++){
            const int n0 = (half*4 + ti)*8;
            const int rbase = blockIdx.x*64 + grp*16 + rquad;
            float2 v0; v0.x = hp[ti][0]; v0.y = hp[ti][1];
            float2 v1; v1.x = hp[ti][2]; v1.y = hp[ti][3];
            *(float2*)(g_hidden + (size_t)rbase*64     + n0 + 2*c) = v0;
            *(float2*)(g_hidden + (size_t)(rbase+8)*64 + n0 + 2*c) = v1;
        }
    }
}

__global__ __launch_bounds__(512) void post_kernel(
    const float* __restrict__ trW, const float* __restrict__ trb, const float* __restrict__ a)
{
    __shared__ float sWt[HH*HH];
    __shared__ float sh[8*HH];
    __shared__ float sa[2*HH];
    __shared__ float sred[16][2];
    int tid = threadIdx.x;
    for (int idx=tid; idx<HH*HH; idx+=512){ int o=idx>>6, k=idx&63; sWt[k*HH+o]=trW[idx]; }
    if (tid < 2*HH) sa[tid] = a[tid];
    int lr = tid>>6, j = tid&63;
    int i = blockIdx.x*8 + lr;
    sh[lr*HH+j] = g_hidden[i*HH+j];
    __syncthreads();
    float acc = trb[j];
    #pragma unroll 8
    for (int k=0; k<HH; k++) acc += sWt[k*HH+j]*sh[lr*HH+k];
    float p1 = acc*sa[j], p2 = acc*sa[HH+j];
    #pragma unroll
    for (int off=16; off; off>>=1){
        p1 += __shfl_down_sync(0xffffffffu, p1, off);
        p2 += __shfl_down_sync(0xffffffffu, p2, off);
    }
    int wid = tid>>5;
    if ((tid&31)==0){ sred[wid][0]=p1; sred[wid][1]=p2; }
    __syncthreads();
    if (tid < 8){
        float s1 = sred[2*tid][0] + sred[2*tid+1][0];
        float s2 = sred[2*tid][1] + sred[2*tid+1][1];
        int n = blockIdx.x*8 + tid;
        g_s1[n] = s1; g_s2[n] = s2;
        unsigned u = f2u(s1);
        g_keys32[n] = ((u >> 13) << 13) | (unsigned)n;
    }
}

__global__ __launch_bounds__(1024) void sort_kernel(){
    extern __shared__ unsigned sk32[];
    int tid = threadIdx.x;
    for (int i=tid; i<NN; i+=1024) sk32[i] = g_keys32[i];
    __syncthreads();
    for (int k=2; k<=NN; k<<=1){
        for (int j=k>>1; j>0; j>>=1){
            for (int i=tid; i<NN; i+=1024){
                int ixj = i^j;
                if (ixj > i){
                    unsigned va = sk32[i], vb = sk32[ixj];
                    bool up = ((i & k) == 0);
                    if ((va > vb) == up){ sk32[i]=vb; sk32[ixj]=va; }
                }
            }
            __syncthreads();
        }
    }
    for (int r=tid; r<NN; r+=1024){
        unsigned key = sk32[r];
        int idx = (int)(key & 8191u);
        g_perm[r]  = idx;
        g_s1s[r]   = g_s1[idx];
        g_ksort[r] = key;
    }
}

__global__ __launch_bounds__(256) void exp_kernel(){
    int i = blockIdx.x*256 + threadIdx.x;
    double v = (double)g_s1s[i];
    g_e1[i]  = exp(v);
    g_e01[i] = exp(0.01*v);
}

__global__ __launch_bounds__(1024) void scan_kernel(){
    __shared__ double ssum[1024];
    int c = blockIdx.x, tid = threadIdx.x;
    int nscans = (c == 128) ? 2 : 1;
    for (int s=0; s<nscans; s++){
        double local[8], ts = 0.0;
        #pragma unroll
        for (int e=0; e<8; e++){
            int r = tid*8 + e;
            double w;
            if (c < 64)       w = g_e1[r]  * (double)g_hidden[g_perm[r]*HH + c];
            else if (c < 128) w = g_e01[r] * (double)g_hidden[g_perm[r]*HH + (c-64)];
            else              w = (s == 0) ? g_e1[r] : g_e01[r];
            local[e] = w; ts += w;
        }
        ssum[tid] = ts; __syncthreads();
        for (int off=1; off<1024; off<<=1){
            double v = ssum[tid];
            if (tid >= off) v += ssum[tid-off];
            __syncthreads(); ssum[tid] = v; __syncthreads();
        }
        double run = tid ? ssum[tid-1] : 0.0;
        #pragma unroll
        for (int e=0; e<8; e++){
            int r = tid*8 + e;
            if (c < 64)       g_prefP[r*HH + c]      = run;
            else if (c < 128) g_prefQ[r*HH + (c-64)] = run;
            else              g_prefE[r*2 + s]        = run;
            run += local[e];
        }
        if (tid == 1023){
            double tot = ssum[1023];
            if (c < 64)       g_prefP[NN*HH + c]      = tot;
            else if (c < 128) g_prefQ[NN*HH + (c-64)] = tot;
            else              g_prefE[NN*2 + s]        = tot;
        }
        __syncthreads();
    }
}

__global__ __launch_bounds__(256) void final_kernel(
    const float* __restrict__ fcW, const float* __restrict__ fcb,
    const float* __restrict__ outW, const float* __restrict__ outb,
    float* __restrict__ out)
{
    __shared__ float sFcT[HH*HH];
    __shared__ float sOw[HH], sFb[HH];
    __shared__ float sH[8][HH];
    int tid = threadIdx.x;
    for (int idx=tid; idx<HH*HH; idx+=256){ int o=idx>>6, k=idx&63; sFcT[k*HH+o]=fcW[idx]; }
    if (tid < HH){ sOw[tid]=outW[tid]; sFb[tid]=fcb[tid]; }
    int w = tid>>5, lane = tid&31;
    int i = blockIdx.x*8 + w;
    float s2 = g_s2[i];
    unsigned thrkey = (f2u(-s2) >> 13) << 13;
    int lo = 0, hi = NN;
    while (lo < hi){ int mid = (lo+hi)>>1; if (g_ksort[mid] < thrkey) lo = mid+1; else hi = mid; }
    int m = lo;
    double e2p = exp((double)s2), e2n = exp(0.01*(double)s2);
    double den = e2p*(g_prefE[NN*2+0] - g_prefE[m*2+0]) + e2n*g_prefE[m*2+1];
    __syncthreads();
    #pragma unroll
    for (int q=0; q<2; q++){
        int d = lane + q*32;
        double Pt = g_prefP[NN*HH + d];
        double num = e2p*(Pt - g_prefP[m*HH + d]) + e2n*g_prefQ[m*HH + d];
        sH[w][d] = (float)(num/den) + g_hidden[i*HH + d];
    }
    __syncwarp();
    float partial = 0.f;
    #pragma unroll
    for (int q=0; q<2; q++){
        int o = lane + q*32;
        float acc = sFb[o];
        #pragma unroll 8
        for (int k=0; k<HH; k++) acc += sFcT[k*HH+o]*sH[w][k];
        acc = (acc >= 0.f) ? acc : 0.01f*acc;
        partial += acc*sOw[o];
    }
    #pragma unroll
    for (int off=16; off; off>>=1) partial += __shfl_down_sync(0xffffffffu, partial, off);
    if (lane == 0) out[i] = partial + outb[0];
}

extern "C" void kernel_launch(void* const* d_in, const int* in_sizes, int n_in,
                              void* d_out, int out_size)
{
    const float* x    = (const float*)d_in[0];
    const float* Wih0 = (const float*)d_in[1];
    const float* Whh0 = (const float*)d_in[2];
    const float* bih0 = (const float*)d_in[3];
    const float* bhh0 = (const float*)d_in[4];
    const float* Wih1 = (const float*)d_in[5];
    const float* Whh1 = (const float*)d_in[6];
    const float* bih1 = (const float*)d_in[7];
    const float* bhh1 = (const float*)d_in[8];
    const float* trW  = (const float*)d_in[9];
    const float* trb  = (const float*)d_in[10];
    const float* a    = (const float*)d_in[11];
    const float* fcW  = (const float*)d_in[12];
    const float* fcb  = (const float*)d_in[13];
    const float* outW = (const float*)d_in[14];
    const float* outb = (const float*)d_in[15];

    cudaFuncSetAttribute(gru_kernel,  cudaFuncAttributeMaxDynamicSharedMemorySize, SMEM_GRU);
    cudaFuncSetAttribute(sort_kernel, cudaFuncAttributeMaxDynamicSharedMemorySize, 32768);

    transpose_kernel<<<NN/32, 256>>>(x);
    gru_kernel<<<128, 512, SMEM_GRU>>>(Wih0, Whh0, bih0, bhh0, Wih1, Whh1, bih1, bhh1);
    post_kernel<<<NN/8, 512>>>(trW, trb, a);
    sort_kernel<<<1, 1024, 32768>>>();
    exp_kernel<<<NN/256, 256>>>();
    scan_kernel<<<129, 1024>>>();
    final_kernel<<<NN/8, 256>>>(fcW, fcb, outW, outb, (float*)d_out);
}

// round 16
// speedup vs baseline: 3.0333x; 1.1641x over previous
#include <cuda_runtime.h>
#include <cuda_fp16.h>
#include <math.h>

#define NN 8192
#define TT 60
#define HH 64

__device__ float g_xt[(size_t)TT*NN*8];
__device__ float g_hidden[NN*HH];
__device__ float g_s1[NN];
__device__ float g_s2[NN];
__device__ unsigned g_keys32[NN];
__device__ unsigned g_schunk[NN];
__device__ unsigned g_ksort[NN];
__device__ float g_s1s[NN];
__device__ int   g_perm[NN];
__device__ double g_e1[NN];
__device__ double g_e01[NN];
__device__ double g_prefP[(NN+1)*HH];
__device__ double g_prefQ[(NN+1)*HH];
__device__ double g_prefE[(NN+1)*2];

__device__ __forceinline__ float tanh_a(float x){
    float t; asm("tanh.approx.f32 %0, %1;" : "=f"(t) : "f"(x)); return t;
}
__device__ __forceinline__ float sig_a(float x){
    float t; asm("tanh.approx.f32 %0, %1;" : "=f"(t) : "f"(0.5f*x));
    return fmaf(t, 0.5f, 0.5f);
}
__device__ __forceinline__ unsigned f2u(float f){
    unsigned u = __float_as_uint(f);
    return (u & 0x80000000u) ? ~u : (u | 0x80000000u);
}
__device__ __forceinline__ unsigned pk2h(float lo, float hi){
    unsigned r;
    asm("{.reg .b16 l,h;\n cvt.rn.f16.f32 l, %1;\n cvt.rn.f16.f32 h, %2;\n mov.b32 %0, {l,h};}"
        : "=r"(r) : "f"(lo), "f"(hi));
    return r;
}
__device__ __forceinline__ unsigned short h16(float v){
    unsigned short s;
    asm("{.reg .b16 t;\n cvt.rn.f16.f32 t, %1;\n mov.b16 %0, t;}" : "=h"(s) : "f"(v));
    return s;
}

#define MMA16(C, A, B0, B1) \
    asm("mma.sync.aligned.m16n8k16.row.col.f32.f16.f16.f32 " \
        "{%0,%1,%2,%3},{%4,%5,%6,%7},{%8,%9},{%0,%1,%2,%3};" \
        : "+f"(C[0]),"+f"(C[1]),"+f"(C[2]),"+f"(C[3]) \
        : "r"((A)[0]),"r"((A)[1]),"r"((A)[2]),"r"((A)[3]),"r"(B0),"r"(B1))

#define MMA8(C, A0, A1, B0) \
    asm("mma.sync.aligned.m16n8k8.row.col.f32.f16.f16.f32 " \
        "{%0,%1,%2,%3},{%4,%5},{%6},{%0,%1,%2,%3};" \
        : "+f"(C[0]),"+f"(C[1]),"+f"(C[2]),"+f"(C[3]) \
        : "r"(A0),"r"(A1),"r"(B0))

#define LDSM4(Q, ADDR) \
    asm volatile("ldmatrix.sync.aligned.m8n8.x4.shared.b16 {%0,%1,%2,%3},[%4];" \
        : "=r"(Q.x),"=r"(Q.y),"=r"(Q.z),"=r"(Q.w) : "r"(ADDR))

#define LDSM4A(A, ADDR) \
    asm volatile("ldmatrix.sync.aligned.m8n8.x4.shared.b16 {%0,%1,%2,%3},[%4];" \
        : "=r"((A)[0]),"=r"((A)[1]),"=r"((A)[2]),"=r"((A)[3]) : "r"(ADDR) : "memory")

#define STS32(ADDR, V) \
    asm volatile("st.shared.u32 [%0], %1;" :: "r"(ADDR), "r"(V) : "memory")

#define XWHI 0
#define W0HI 3072
#define WI1HI 30720
#define WH1HI 58368
#define BIASO 86016
#define S0HI 88064
#define S1HI 106496
#define SMEM_GRU 124928

__device__ __forceinline__ unsigned smem_u32(const void* p){
    unsigned a; asm("{ .reg .u64 t; cvta.to.shared.u64 t, %1; cvt.u32.u64 %0, t; }" : "=r"(a) : "l"(p));
    return a;
}

#define GATE_EPIR(Cr,Cz,Ci,Chn, BOFF, n0_, HP, SH_) do{ \
    float2 _br = *(const float2*)(sbias + (BOFF) + (n0_) + 2*c); \
    float2 _bz = *(const float2*)(sbias + (BOFF) + 64 + (n0_) + 2*c); \
    float2 _bi = *(const float2*)(sbias + (BOFF) + 128 + (n0_) + 2*c); \
    float2 _bh = *(const float2*)(sbias + (BOFF) + 192 + (n0_) + 2*c); \
    float _r0=sig_a(Cr[0]+_br.x), _r1=sig_a(Cr[1]+_br.y), _r2=sig_a(Cr[2]+_br.x), _r3=sig_a(Cr[3]+_br.y); \
    float _z0=sig_a(Cz[0]+_bz.x), _z1=sig_a(Cz[1]+_bz.y), _z2=sig_a(Cz[2]+_bz.x), _z3=sig_a(Cz[3]+_bz.y); \
    float _n0=tanh_a(Ci[0]+_bi.x+_r0*(Chn[0]+_bh.x)); \
    float _n1=tanh_a(Ci[1]+_bi.y+_r1*(Chn[1]+_bh.y)); \
    float _n2=tanh_a(Ci[2]+_bi.x+_r2*(Chn[2]+_bh.x)); \
    float _n3=tanh_a(Ci[3]+_bi.y+_r3*(Chn[3]+_bh.y)); \
    float _h0=_n0+_z0*((HP)[0]-_n0), _h1=_n1+_z1*((HP)[1]-_n1); \
    float _h2=_n2+_z2*((HP)[2]-_n2), _h3=_n3+_z3*((HP)[3]-_n3); \
    (HP)[0]=_h0; (HP)[1]=_h1; (HP)[2]=_h2; (HP)[3]=_h3; \
    STS32((SH_) + (n0_)*2,        pk2h(_h0,_h1)); \
    STS32((SH_) + (n0_)*2 + 1152, pk2h(_h2,_h3)); \
}while(0)

#define L0_TILE(t8, XH0,XH1) do{ \
    const int n0 = (t8)*8; \
    float Cr[4]={0,0,0,0}, Cz[4]={0,0,0,0}, Ci[4]={0,0,0,0}, Chn[4]={0,0,0,0}; \
    uint4 qx; LDSM4(qx, a_x + n0*16); \
    MMA8(Cr,XH0,XH1,qx.x); MMA8(Cz,XH0,XH1,qx.y); MMA8(Ci,XH0,XH1,qx.z); \
    _Pragma("unroll") \
    for (int kp=0; kp<2; kp++){ \
        uint4 qr, qz, qn; \
        LDSM4(qr, a_w0 + n0*144 + kp*64); \
        LDSM4(qz, a_w0 + 9216 + n0*144 + kp*64); \
        LDSM4(qn, a_w0 + 18432 + n0*144 + kp*64); \
        const int k0 = 2*kp; \
        MMA16(Cr, a0h[k0], qr.x, qr.y); MMA16(Cz, a0h[k0], qz.x, qz.y); MMA16(Chn, a0h[k0], qn.x, qn.y); \
        MMA16(Cr, a0h[k0+1], qr.z, qr.w); MMA16(Cz, a0h[k0+1], qz.z, qz.w); MMA16(Chn, a0h[k0+1], qn.z, qn.w); \
    } \
    GATE_EPIR(Cr,Cz,Ci,Chn, 0, n0, hp[(t8)&3], st0h); \
}while(0)

#define L1_TILE(t8) do{ \
    const int n0 = (t8)*8; \
    float Cri[4]={0,0,0,0}, Crh[4]={0,0,0,0}, Czi[4]={0,0,0,0}, Czh[4]={0,0,0,0}; \
    float Cii[4]={0,0,0,0}, Chn[4]={0,0,0,0}; \
    _Pragma("unroll") \
    for (int kp=0; kp<2; kp++){ \
        uint4 q0,q1,q2,q3,q4,q5; \
        LDSM4(q0, a_i1 + n0*144 + kp*64); \
        LDSM4(q1, a_h1 + n0*144 + kp*64); \
        LDSM4(q2, a_i1 + 9216 + n0*144 + kp*64); \
        LDSM4(q3, a_h1 + 9216 + n0*144 + kp*64); \
        LDSM4(q4, a_i1 + 18432 + n0*144 + kp*64); \
        LDSM4(q5, a_h1 + 18432 + n0*144 + kp*64); \
        const int k0 = 2*kp; \
        MMA16(Cri, yh[k0], q0.x, q0.y); MMA16(Crh, a1h[k0], q1.x, q1.y); \
        MMA16(Czi, yh[k0], q2.x, q2.y); MMA16(Czh, a1h[k0], q3.x, q3.y); \
        MMA16(Cii, yh[k0], q4.x, q4.y); MMA16(Chn, a1h[k0], q5.x, q5.y); \
        MMA16(Cri, yh[k0+1], q0.z, q0.w); MMA16(Crh, a1h[k0+1], q1.z, q1.w); \
        MMA16(Czi, yh[k0+1], q2.z, q2.w); MMA16(Czh, a1h[k0+1], q3.z, q3.w); \
        MMA16(Cii, yh[k0+1], q4.z, q4.w); MMA16(Chn, a1h[k0+1], q5.z, q5.w); \
    } \
    float Cr[4], Cz[4]; \
    _Pragma("unroll") \
    for (int i=0;i<4;i++){ Cr[i]=Cri[i]+Crh[i]; Cz[i]=Czi[i]+Czh[i]; } \
    GATE_EPIR(Cr,Cz,Cii,Chn, 256, n0, hp[(t8)&3], st1h); \
}while(0)

__global__ __launch_bounds__(256) void transpose_kernel(const float* __restrict__ x){
    __shared__ float sx[32*360];
    int nb = blockIdx.x*32, tid = threadIdx.x;
    for (int idx=tid; idx<32*360; idx+=256) sx[idx] = x[(size_t)nb*360 + idx];
    __syncthreads();
    int n = tid>>3, d = tid&7;
    float* op = g_xt + ((size_t)(nb+n))*8 + d;
    #pragma unroll 4
    for (int t=0; t<TT; t++)
        op[(size_t)t*NN*8] = (d<6) ? sx[n*360 + d*60 + t] : 0.f;
}

__global__ __launch_bounds__(512,1) void gru_kernel(
    const float* __restrict__ Wih0, const float* __restrict__ Whh0,
    const float* __restrict__ bih0, const float* __restrict__ bhh0,
    const float* __restrict__ Wih1, const float* __restrict__ Whh1,
    const float* __restrict__ bih1, const float* __restrict__ bhh1)
{
    extern __shared__ char sm[];
    const int tid = threadIdx.x;
    unsigned short* xw = (unsigned short*)(sm + XWHI);
    for (int i=tid; i<1536; i+=512) xw[i]=0;
    for (int i=tid; i<1152; i+=512){
        int n = i/6, d = i - n*6;
        xw[n*8+d] = h16(Wih0[i]);
    }
    {
        unsigned short* w0 = (unsigned short*)(sm + W0HI);
        unsigned short* i1 = (unsigned short*)(sm + WI1HI);
        unsigned short* h1 = (unsigned short*)(sm + WH1HI);
        for (int i=tid; i<12288; i+=512){
            int n = i>>6, k = i&63, o = n*72+k;
            w0[o] = h16(Whh0[i]);
            i1[o] = h16(Wih1[i]);
            h1[o] = h16(Whh1[i]);
        }
    }
    for (int i=tid; i<36864/4; i+=512) ((unsigned*)(sm + S0HI))[i] = 0u;
    float* sbias = (float*)(sm + BIASO);
    if (tid < 64){
        int j = tid;
        sbias[j]     = bih0[j]    + bhh0[j];
        sbias[64+j]  = bih0[64+j] + bhh0[64+j];
        sbias[128+j] = bih0[128+j];
        sbias[192+j] = bhh0[128+j];
        sbias[256+j] = bih1[j]    + bhh1[j];
        sbias[320+j] = bih1[64+j] + bhh1[64+j];
        sbias[384+j] = bih1[128+j];
        sbias[448+j] = bhh1[128+j];
    }
    __syncthreads();

    const int lane = tid & 31, warp = tid >> 5;
    const int grp = warp & 3;
    const int role = warp >> 2;
    const int half = role & 1;
    const int rquad = lane >> 2, c = lane & 3;
    const int row0 = blockIdx.x*64 + grp*16 + rquad;
    const unsigned smb = smem_u32(sm);
    const int sub = lane >> 3, r8 = lane & 7;
    const unsigned soff = r8*144 + sub*16;
    const unsigned a_w0 = smb + W0HI  + soff;
    const unsigned a_i1 = smb + WI1HI + soff;
    const unsigned a_h1 = smb + WH1HI + soff;
    const unsigned xgrow = (sub==0) ? 0u : (sub==1 ? 64u : 128u);
    const unsigned a_x = smb + XWHI + (xgrow + r8)*16;

    const unsigned lsl = (lane & 15)*144 + (lane >> 4)*16;
    const unsigned stb = grp*2304 + rquad*144 + 4*c;

    float hp[4][4];
    #pragma unroll
    for (int a=0;a<4;a++)
        #pragma unroll
        for (int b=0;b<4;b++) hp[a][b] = 0.f;

    #pragma unroll 1
    for (int it=0; it<=TT; it++){
        if (role < 2 && it < TT){
            const int t = it;
            const unsigned rd = (unsigned)(((t+1)&1)*9216);
            const unsigned wr = (unsigned)((t&1)*9216);
            unsigned a0h[4][4];
            #pragma unroll
            for (int kt=0;kt<4;kt++)
                LDSM4A(a0h[kt], smb + S0HI + rd + grp*2304 + lsl + kt*32);
            const float* _xp = g_xt + ((size_t)t*NN + row0)*8 + 2*c;
            float2 _x0 = *(const float2*)_xp;
            float2 _x1 = *(const float2*)(_xp + 64);
            unsigned xh0 = pk2h(_x0.x, _x0.y);
            unsigned xh1 = pk2h(_x1.x, _x1.y);
            const unsigned st0h = smb + S0HI + wr + stb;
            if (!half){
                #pragma unroll
                for (int t8=0; t8<4; t8++) L0_TILE(t8, xh0,xh1);
            } else {
                #pragma unroll
                for (int t8=4; t8<8; t8++) L0_TILE(t8, xh0,xh1);
            }
        }
        if (role >= 2 && it >= 1){
            const int t = it - 1;
            const unsigned rd0 = (unsigned)((t&1)*9216);
            const unsigned rd1 = (unsigned)(((t+1)&1)*9216);
            const unsigned wr1 = (unsigned)((t&1)*9216);
            unsigned yh[4][4], a1h[4][4];
            #pragma unroll
            for (int kt=0;kt<4;kt++){
                LDSM4A(yh[kt],  smb + S0HI + rd0 + grp*2304 + lsl + kt*32);
                LDSM4A(a1h[kt], smb + S1HI + rd1 + grp*2304 + lsl + kt*32);
            }
            const unsigned st1h = smb + S1HI + wr1 + stb;
            if (!half){
                #pragma unroll
                for (int t8=0; t8<4; t8++) L1_TILE(t8);
            } else {
                #pragma unroll
                for (int t8=4; t8<8; t8++) L1_TILE(t8);
            }
        }
        __syncthreads();
    }

    if (role >= 2){
        #pragma unroll
        for (int ti=0; ti<4; ti++){
            const int n0 = (half*4 + ti)*8;
            const int rbase = blockIdx.x*64 + grp*16 + rquad;
            float2 v0; v0.x = hp[ti][0]; v0.y = hp[ti][1];
            float2 v1; v1.x = hp[ti][2]; v1.y = hp[ti][3];
            *(float2*)(g_hidden + (size_t)rbase*64     + n0 + 2*c) = v0;
            *(float2*)(g_hidden + (size_t)(rbase+8)*64 + n0 + 2*c) = v1;
        }
    }
}

__global__ __launch_bounds__(512) void post_kernel(
    const float* __restrict__ trW, const float* __restrict__ trb, const float* __restrict__ a)
{
    __shared__ float sWt[HH*HH];
    __shared__ float sh[8*HH];
    __shared__ float sa[2*HH];
    __shared__ float sred[16][2];
    int tid = threadIdx.x;
    for (int idx=tid; idx<HH*HH; idx+=512){ int o=idx>>6, k=idx&63; sWt[k*HH+o]=trW[idx]; }
    if (tid < 2*HH) sa[tid] = a[tid];
    int lr = tid>>6, j = tid&63;
    int i = blockIdx.x*8 + lr;
    sh[lr*HH+j] = g_hidden[i*HH+j];
    __syncthreads();
    float acc = trb[j];
    #pragma unroll 8
    for (int k=0; k<HH; k++) acc += sWt[k*HH+j]*sh[lr*HH+k];
    float p1 = acc*sa[j], p2 = acc*sa[HH+j];
    #pragma unroll
    for (int off=16; off; off>>=1){
        p1 += __shfl_down_sync(0xffffffffu, p1, off);
        p2 += __shfl_down_sync(0xffffffffu, p2, off);
    }
    int wid = tid>>5;
    if ((tid&31)==0){ sred[wid][0]=p1; sred[wid][1]=p2; }
    __syncthreads();
    if (tid < 8){
        float s1 = sred[2*tid][0] + sred[2*tid+1][0];
        float s2 = sred[2*tid][1] + sred[2*tid+1][1];
        int n = blockIdx.x*8 + tid;
        g_s1[n] = s1; g_s2[n] = s2;
        unsigned u = f2u(s1);
        g_keys32[n] = ((u >> 13) << 13) | (unsigned)n;
    }
}

// 8 blocks: each bitonically sorts its 1024-key chunk in smem
__global__ __launch_bounds__(1024) void sortA_kernel(){
    __shared__ unsigned sk[1024];
    int b = blockIdx.x, tid = threadIdx.x;
    sk[tid] = g_keys32[b*1024 + tid];
    __syncthreads();
    for (int k=2; k<=1024; k<<=1){
        for (int j=k>>1; j>0; j>>=1){
            int ixj = tid^j;
            if (ixj > tid){
                unsigned va = sk[tid], vb = sk[ixj];
                bool up = ((tid & k) == 0);
                if ((va > vb) == up){ sk[tid]=vb; sk[ixj]=va; }
            }
            __syncthreads();
        }
    }
    g_schunk[b*1024 + tid] = sk[tid];
}

// rank-merge: global rank = local pos + lower_bound in the 7 other chunks
__global__ __launch_bounds__(256) void sortB_kernel(){
    int i = blockIdx.x*256 + threadIdx.x;
    int b = i >> 10;
    unsigned key = g_schunk[i];
    int rank = i & 1023;
    #pragma unroll 1
    for (int ob=0; ob<8; ob++){
        if (ob == b) continue;
        const unsigned* ch = g_schunk + ob*1024;
        int lo = 0, hi = 1024;
        while (lo < hi){ int mid = (lo+hi)>>1; if (ch[mid] < key) lo = mid+1; else hi = mid; }
        rank += lo;
    }
    int idx = (int)(key & 8191u);
    g_perm[rank]  = idx;
    g_s1s[rank]   = g_s1[idx];
    g_ksort[rank] = key;
}

__global__ __launch_bounds__(256) void exp_kernel(){
    int i = blockIdx.x*256 + threadIdx.x;
    double v = (double)g_s1s[i];
    g_e1[i]  = exp(v);
    g_e01[i] = exp(0.01*v);
}

__global__ __launch_bounds__(1024) void scan_kernel(){
    __shared__ double wsum[32];
    __shared__ double sbase[33];
    int c = blockIdx.x, tid = threadIdx.x;
    int lane = tid & 31, wid = tid >> 5;
    int nscans = (c == 128) ? 2 : 1;
    for (int s=0; s<nscans; s++){
        double local[8], ts = 0.0;
        #pragma unroll
        for (int e=0; e<8; e++){
            int r = tid*8 + e;
            double w;
            if (c < 64)       w = g_e1[r]  * (double)g_hidden[g_perm[r]*HH + c];
            else if (c < 128) w = g_e01[r] * (double)g_hidden[g_perm[r]*HH + (c-64)];
            else              w = (s == 0) ? g_e1[r] : g_e01[r];
            local[e] = w; ts += w;
        }
        // warp inclusive scan
        double incl = ts;
        #pragma unroll
        for (int off=1; off<32; off<<=1){
            double v = __shfl_up_sync(0xffffffffu, incl, off);
            if (lane >= off) incl += v;
        }
        if (lane == 31) wsum[wid] = incl;
        __syncthreads();
        if (wid == 0){
            double iv = wsum[lane];
            #pragma unroll
            for (int off=1; off<32; off<<=1){
                double u = __shfl_up_sync(0xffffffffu, iv, off);
                if (lane >= off) iv += u;
            }
            sbase[lane+1] = iv;
            if (lane == 0) sbase[0] = 0.0;
        }
        __syncthreads();
        double run = sbase[wid] + (incl - ts);
        #pragma unroll
        for (int e=0; e<8; e++){
            int r = tid*8 + e;
            if (c < 64)       g_prefP[r*HH + c]      = run;
            else if (c < 128) g_prefQ[r*HH + (c-64)] = run;
            else              g_prefE[r*2 + s]        = run;
            run += local[e];
        }
        if (tid == 0){
            double tot = sbase[32];
            if (c < 64)       g_prefP[NN*HH + c]      = tot;
            else if (c < 128) g_prefQ[NN*HH + (c-64)] = tot;
            else              g_prefE[NN*2 + s]        = tot;
        }
        __syncthreads();
    }
}

__global__ __launch_bounds__(256) void final_kernel(
    const float* __restrict__ fcW, const float* __restrict__ fcb,
    const float* __restrict__ outW, const float* __restrict__ outb,
    float* __restrict__ out)
{
    __shared__ float sFcT[HH*HH];
    __shared__ float sOw[HH], sFb[HH];
    __shared__ float sH[8][HH];
    int tid = threadIdx.x;
    for (int idx=tid; idx<HH*HH; idx+=256){ int o=idx>>6, k=idx&63; sFcT[k*HH+o]=fcW[idx]; }
    if (tid < HH){ sOw[tid]=outW[tid]; sFb[tid]=fcb[tid]; }
    int w = tid>>5, lane = tid&31;
    int i = blockIdx.x*8 + w;
    float s2 = g_s2[i];
    unsigned thrkey = (f2u(-s2) >> 13) << 13;
    int lo = 0, hi = NN;
    while (lo < hi){ int mid = (lo+hi)>>1; if (g_ksort[mid] < thrkey) lo = mid+1; else hi = mid; }
    int m = lo;
    double e2p = exp((double)s2), e2n = exp(0.01*(double)s2);
    double den = e2p*(g_prefE[NN*2+0] - g_prefE[m*2+0]) + e2n*g_prefE[m*2+1];
    __syncthreads();
    #pragma unroll
    for (int q=0; q<2; q++){
        int d = lane + q*32;
        double Pt = g_prefP[NN*HH + d];
        double num = e2p*(Pt - g_prefP[m*HH + d]) + e2n*g_prefQ[m*HH + d];
        sH[w][d] = (float)(num/den) + g_hidden[i*HH + d];
    }
    __syncwarp();
    float partial = 0.f;
    #pragma unroll
    for (int q=0; q<2; q++){
        int o = lane + q*32;
        float acc = sFb[o];
        #pragma unroll 8
        for (int k=0; k<HH; k++) acc += sFcT[k*HH+o]*sH[w][k];
        acc = (acc >= 0.f) ? acc : 0.01f*acc;
        partial += acc*sOw[o];
    }
    #pragma unroll
    for (int off=16; off; off>>=1) partial += __shfl_down_sync(0xffffffffu, partial, off);
    if (lane == 0) out[i] = partial + outb[0];
}

extern "C" void kernel_launch(void* const* d_in, const int* in_sizes, int n_in,
                              void* d_out, int out_size)
{
    const float* x    = (const float*)d_in[0];
    const float* Wih0 = (const float*)d_in[1];
    const float* Whh0 = (const float*)d_in[2];
    const float* bih0 = (const float*)d_in[3];
    const float* bhh0 = (const float*)d_in[4];
    const float* Wih1 = (const float*)d_in[5];
    const float* Whh1 = (const float*)d_in[6];
    const float* bih1 = (const float*)d_in[7];
    const float* bhh1 = (const float*)d_in[8];
    const float* trW  = (const float*)d_in[9];
    const float* trb  = (const float*)d_in[10];
    const float* a    = (const float*)d_in[11];
    const float* fcW  = (const float*)d_in[12];
    const float* fcb  = (const float*)d_in[13];
    const float* outW = (const float*)d_in[14];
    const float* outb = (const float*)d_in[15];

    cudaFuncSetAttribute(gru_kernel, cudaFuncAttributeMaxDynamicSharedMemorySize, SMEM_GRU);

    transpose_kernel<<<NN/32, 256>>>(x);
    gru_kernel<<<128, 512, SMEM_GRU>>>(Wih0, Whh0, bih0, bhh0, Wih1, Whh1, bih1, bhh1);
    post_kernel<<<NN/8, 512>>>(trW, trb, a);
    sortA_kernel<<<8, 1024>>>();
    sortB_kernel<<<NN/256, 256>>>();
    exp_kernel<<<NN/256, 256>>>();
    scan_kernel<<<129, 1024>>>();
    final_kernel<<<NN/8, 256>>>(fcW, fcb, outW, outb, (float*)d_out);
}

// round 17
// speedup vs baseline: 3.1730x; 1.0460x over previous
#include <cuda_runtime.h>
#include <cuda_fp16.h>
#include <math.h>

#define NN 8192
#define TT 60
#define HH 64

__device__ float g_xt[(size_t)TT*NN*8];
__device__ float g_hidden[NN*HH];
__device__ float g_s1[NN];
__device__ float g_s2[NN];
__device__ unsigned g_keys32[NN];
__device__ unsigned g_schunk[NN];
__device__ unsigned g_ksort[NN];
__device__ float g_s1s[NN];
__device__ int   g_perm[NN];
__device__ double g_e1[NN];
__device__ double g_e01[NN];
__device__ double g_prefP[(NN+1)*HH];
__device__ double g_prefQ[(NN+1)*HH];
__device__ double g_prefE[(NN+1)*2];

__device__ __forceinline__ float tanh_a(float x){
    float t; asm("tanh.approx.f32 %0, %1;" : "=f"(t) : "f"(x)); return t;
}
__device__ __forceinline__ float sig_a(float x){
    float t; asm("tanh.approx.f32 %0, %1;" : "=f"(t) : "f"(0.5f*x));
    return fmaf(t, 0.5f, 0.5f);
}
__device__ __forceinline__ unsigned f2u(float f){
    unsigned u = __float_as_uint(f);
    return (u & 0x80000000u) ? ~u : (u | 0x80000000u);
}
__device__ __forceinline__ unsigned pk2h(float lo, float hi){
    unsigned r;
    asm("{.reg .b16 l,h;\n cvt.rn.f16.f32 l, %1;\n cvt.rn.f16.f32 h, %2;\n mov.b32 %0, {l,h};}"
        : "=r"(r) : "f"(lo), "f"(hi));
    return r;
}
__device__ __forceinline__ unsigned short h16(float v){
    unsigned short s;
    asm("{.reg .b16 t;\n cvt.rn.f16.f32 t, %1;\n mov.b16 %0, t;}" : "=h"(s) : "f"(v));
    return s;
}

#define MMA16(C, A, B0, B1) \
    asm("mma.sync.aligned.m16n8k16.row.col.f32.f16.f16.f32 " \
        "{%0,%1,%2,%3},{%4,%5,%6,%7},{%8,%9},{%0,%1,%2,%3};" \
        : "+f"(C[0]),"+f"(C[1]),"+f"(C[2]),"+f"(C[3]) \
        : "r"((A)[0]),"r"((A)[1]),"r"((A)[2]),"r"((A)[3]),"r"(B0),"r"(B1))

#define MMA8(C, A0, A1, B0) \
    asm("mma.sync.aligned.m16n8k8.row.col.f32.f16.f16.f32 " \
        "{%0,%1,%2,%3},{%4,%5},{%6},{%0,%1,%2,%3};" \
        : "+f"(C[0]),"+f"(C[1]),"+f"(C[2]),"+f"(C[3]) \
        : "r"(A0),"r"(A1),"r"(B0))

#define LDSM4(Q, ADDR) \
    asm volatile("ldmatrix.sync.aligned.m8n8.x4.shared.b16 {%0,%1,%2,%3},[%4];" \
        : "=r"(Q.x),"=r"(Q.y),"=r"(Q.z),"=r"(Q.w) : "r"(ADDR))

#define LDSM4A(A, ADDR) \
    asm volatile("ldmatrix.sync.aligned.m8n8.x4.shared.b16 {%0,%1,%2,%3},[%4];" \
        : "=r"((A)[0]),"=r"((A)[1]),"=r"((A)[2]),"=r"((A)[3]) : "r"(ADDR) : "memory")

#define STS32(ADDR, V) \
    asm volatile("st.shared.u32 [%0], %1;" :: "r"(ADDR), "r"(V) : "memory")

#define XWHI 0
#define W0HI 3072
#define WI1HI 30720
#define WH1HI 58368
#define BIASO 86016
#define S0HI 88064
#define S1HI 106496
#define SMEM_GRU 124928

__device__ __forceinline__ unsigned smem_u32(const void* p){
    unsigned a; asm("{ .reg .u64 t; cvta.to.shared.u64 t, %1; cvt.u32.u64 %0, t; }" : "=r"(a) : "l"(p));
    return a;
}

#define GATE_EPIR(Cr,Cz,Ci,Chn, BOFF, n0_, HP, SH_) do{ \
    float2 _br = *(const float2*)(sbias + (BOFF) + (n0_) + 2*c); \
    float2 _bz = *(const float2*)(sbias + (BOFF) + 64 + (n0_) + 2*c); \
    float2 _bi = *(const float2*)(sbias + (BOFF) + 128 + (n0_) + 2*c); \
    float2 _bh = *(const float2*)(sbias + (BOFF) + 192 + (n0_) + 2*c); \
    float _r0=sig_a(Cr[0]+_br.x), _r1=sig_a(Cr[1]+_br.y), _r2=sig_a(Cr[2]+_br.x), _r3=sig_a(Cr[3]+_br.y); \
    float _z0=sig_a(Cz[0]+_bz.x), _z1=sig_a(Cz[1]+_bz.y), _z2=sig_a(Cz[2]+_bz.x), _z3=sig_a(Cz[3]+_bz.y); \
    float _n0=tanh_a(Ci[0]+_bi.x+_r0*(Chn[0]+_bh.x)); \
    float _n1=tanh_a(Ci[1]+_bi.y+_r1*(Chn[1]+_bh.y)); \
    float _n2=tanh_a(Ci[2]+_bi.x+_r2*(Chn[2]+_bh.x)); \
    float _n3=tanh_a(Ci[3]+_bi.y+_r3*(Chn[3]+_bh.y)); \
    float _h0=_n0+_z0*((HP)[0]-_n0), _h1=_n1+_z1*((HP)[1]-_n1); \
    float _h2=_n2+_z2*((HP)[2]-_n2), _h3=_n3+_z3*((HP)[3]-_n3); \
    (HP)[0]=_h0; (HP)[1]=_h1; (HP)[2]=_h2; (HP)[3]=_h3; \
    STS32((SH_) + (n0_)*2,        pk2h(_h0,_h1)); \
    STS32((SH_) + (n0_)*2 + 1152, pk2h(_h2,_h3)); \
}while(0)

#define L0_TILE(t8, XH0,XH1) do{ \
    const int n0 = (t8)*8; \
    float Cr[4]={0,0,0,0}, Cz[4]={0,0,0,0}, Ci[4]={0,0,0,0}, Chn[4]={0,0,0,0}; \
    uint4 qx; LDSM4(qx, a_x + n0*16); \
    MMA8(Cr,XH0,XH1,qx.x); MMA8(Cz,XH0,XH1,qx.y); MMA8(Ci,XH0,XH1,qx.z); \
    _Pragma("unroll") \
    for (int kp=0; kp<2; kp++){ \
        uint4 qr, qz, qn; \
        LDSM4(qr, a_w0 + n0*144 + kp*64); \
        LDSM4(qz, a_w0 + 9216 + n0*144 + kp*64); \
        LDSM4(qn, a_w0 + 18432 + n0*144 + kp*64); \
        const int k0 = 2*kp; \
        MMA16(Cr, a0h[k0], qr.x, qr.y); MMA16(Cz, a0h[k0], qz.x, qz.y); MMA16(Chn, a0h[k0], qn.x, qn.y); \
        MMA16(Cr, a0h[k0+1], qr.z, qr.w); MMA16(Cz, a0h[k0+1], qz.z, qz.w); MMA16(Chn, a0h[k0+1], qn.z, qn.w); \
    } \
    GATE_EPIR(Cr,Cz,Ci,Chn, 0, n0, hp[(t8)&3], st0h); \
}while(0)

#define L1_TILE(t8) do{ \
    const int n0 = (t8)*8; \
    float Cri[4]={0,0,0,0}, Crh[4]={0,0,0,0}, Czi[4]={0,0,0,0}, Czh[4]={0,0,0,0}; \
    float Cii[4]={0,0,0,0}, Chn[4]={0,0,0,0}; \
    _Pragma("unroll") \
    for (int kp=0; kp<2; kp++){ \
        uint4 q0,q1,q2,q3,q4,q5; \
        LDSM4(q0, a_i1 + n0*144 + kp*64); \
        LDSM4(q1, a_h1 + n0*144 + kp*64); \
        LDSM4(q2, a_i1 + 9216 + n0*144 + kp*64); \
        LDSM4(q3, a_h1 + 9216 + n0*144 + kp*64); \
        LDSM4(q4, a_i1 + 18432 + n0*144 + kp*64); \
        LDSM4(q5, a_h1 + 18432 + n0*144 + kp*64); \
        const int k0 = 2*kp; \
        MMA16(Cri, yh[k0], q0.x, q0.y); MMA16(Crh, a1h[k0], q1.x, q1.y); \
        MMA16(Czi, yh[k0], q2.x, q2.y); MMA16(Czh, a1h[k0], q3.x, q3.y); \
        MMA16(Cii, yh[k0], q4.x, q4.y); MMA16(Chn, a1h[k0], q5.x, q5.y); \
        MMA16(Cri, yh[k0+1], q0.z, q0.w); MMA16(Crh, a1h[k0+1], q1.z, q1.w); \
        MMA16(Czi, yh[k0+1], q2.z, q2.w); MMA16(Czh, a1h[k0+1], q3.z, q3.w); \
        MMA16(Cii, yh[k0+1], q4.z, q4.w); MMA16(Chn, a1h[k0+1], q5.z, q5.w); \
    } \
    float Cr[4], Cz[4]; \
    _Pragma("unroll") \
    for (int i=0;i<4;i++){ Cr[i]=Cri[i]+Crh[i]; Cz[i]=Czi[i]+Czh[i]; } \
    GATE_EPIR(Cr,Cz,Cii,Chn, 256, n0, hp[(t8)&3], st1h); \
}while(0)

__global__ __launch_bounds__(256) void transpose_kernel(const float* __restrict__ x){
    __shared__ float sx[32*360];
    int nb = blockIdx.x*32, tid = threadIdx.x;
    for (int idx=tid; idx<32*360; idx+=256) sx[idx] = x[(size_t)nb*360 + idx];
    __syncthreads();
    int n = tid>>3, d = tid&7;
    float* op = g_xt + ((size_t)(nb+n))*8 + d;
    #pragma unroll 4
    for (int t=0; t<TT; t++)
        op[(size_t)t*NN*8] = (d<6) ? sx[n*360 + d*60 + t] : 0.f;
}

__global__ __launch_bounds__(512,1) void gru_kernel(
    const float* __restrict__ Wih0, const float* __restrict__ Whh0,
    const float* __restrict__ bih0, const float* __restrict__ bhh0,
    const float* __restrict__ Wih1, const float* __restrict__ Whh1,
    const float* __restrict__ bih1, const float* __restrict__ bhh1,
    const float* __restrict__ trW, const float* __restrict__ trb,
    const float* __restrict__ av)
{
    extern __shared__ char sm[];
    const int tid = threadIdx.x;
    unsigned short* xw = (unsigned short*)(sm + XWHI);
    for (int i=tid; i<1536; i+=512) xw[i]=0;
    for (int i=tid; i<1152; i+=512){
        int n = i/6, d = i - n*6;
        xw[n*8+d] = h16(Wih0[i]);
    }
    {
        unsigned short* w0 = (unsigned short*)(sm + W0HI);
        unsigned short* i1 = (unsigned short*)(sm + WI1HI);
        unsigned short* h1 = (unsigned short*)(sm + WH1HI);
        for (int i=tid; i<12288; i+=512){
            int n = i>>6, k = i&63, o = n*72+k;
            w0[o] = h16(Whh0[i]);
            i1[o] = h16(Wih1[i]);
            h1[o] = h16(Whh1[i]);
        }
    }
    for (int i=tid; i<36864/4; i+=512) ((unsigned*)(sm + S0HI))[i] = 0u;
    float* sbias = (float*)(sm + BIASO);
    if (tid < 64){
        int j = tid;
        sbias[j]     = bih0[j]    + bhh0[j];
        sbias[64+j]  = bih0[64+j] + bhh0[64+j];
        sbias[128+j] = bih0[128+j];
        sbias[192+j] = bhh0[128+j];
        sbias[256+j] = bih1[j]    + bhh1[j];
        sbias[320+j] = bih1[64+j] + bhh1[64+j];
        sbias[384+j] = bih1[128+j];
        sbias[448+j] = bhh1[128+j];
    }
    __syncthreads();

    const int lane = tid & 31, warp = tid >> 5;
    const int grp = warp & 3;
    const int role = warp >> 2;
    const int half = role & 1;
    const int rquad = lane >> 2, c = lane & 3;
    const int row0 = blockIdx.x*64 + grp*16 + rquad;
    const unsigned smb = smem_u32(sm);
    const int sub = lane >> 3, r8 = lane & 7;
    const unsigned soff = r8*144 + sub*16;
    const unsigned a_w0 = smb + W0HI  + soff;
    const unsigned a_i1 = smb + WI1HI + soff;
    const unsigned a_h1 = smb + WH1HI + soff;
    const unsigned xgrow = (sub==0) ? 0u : (sub==1 ? 64u : 128u);
    const unsigned a_x = smb + XWHI + (xgrow + r8)*16;

    const unsigned lsl = (lane & 15)*144 + (lane >> 4)*16;
    const unsigned stb = grp*2304 + rquad*144 + 4*c;

    float hp[4][4];
    #pragma unroll
    for (int a=0;a<4;a++)
        #pragma unroll
        for (int b=0;b<4;b++) hp[a][b] = 0.f;

    #pragma unroll 1
    for (int it=0; it<=TT; it++){
        if (role < 2 && it < TT){
            const int t = it;
            const unsigned rd = (unsigned)(((t+1)&1)*9216);
            const unsigned wr = (unsigned)((t&1)*9216);
            unsigned a0h[4][4];
            #pragma unroll
            for (int kt=0;kt<4;kt++)
                LDSM4A(a0h[kt], smb + S0HI + rd + grp*2304 + lsl + kt*32);
            const float* _xp = g_xt + ((size_t)t*NN + row0)*8 + 2*c;
            float2 _x0 = *(const float2*)_xp;
            float2 _x1 = *(const float2*)(_xp + 64);
            unsigned xh0 = pk2h(_x0.x, _x0.y);
            unsigned xh1 = pk2h(_x1.x, _x1.y);
            const unsigned st0h = smb + S0HI + wr + stb;
            if (!half){
                #pragma unroll
                for (int t8=0; t8<4; t8++) L0_TILE(t8, xh0,xh1);
            } else {
                #pragma unroll
                for (int t8=4; t8<8; t8++) L0_TILE(t8, xh0,xh1);
            }
        }
        if (role >= 2 && it >= 1){
            const int t = it - 1;
            const unsigned rd0 = (unsigned)((t&1)*9216);
            const unsigned rd1 = (unsigned)(((t+1)&1)*9216);
            const unsigned wr1 = (unsigned)((t&1)*9216);
            unsigned yh[4][4], a1h[4][4];
            #pragma unroll
            for (int kt=0;kt<4;kt++){
                LDSM4A(yh[kt],  smb + S0HI + rd0 + grp*2304 + lsl + kt*32);
                LDSM4A(a1h[kt], smb + S1HI + rd1 + grp*2304 + lsl + kt*32);
            }
            const unsigned st1h = smb + S1HI + wr1 + stb;
            if (!half){
                #pragma unroll
                for (int t8=0; t8<4; t8++) L1_TILE(t8);
            } else {
                #pragma unroll
                for (int t8=4; t8<8; t8++) L1_TILE(t8);
            }
        }
        __syncthreads();
    }

    // ---- fused epilogue: write h, then compute t = h@trW^T, s1, s2, keys ----
    float* sh = (float*)(sm + S0HI);   // 64 rows x 65 stride fp32
    if (role >= 2){
        #pragma unroll
        for (int ti=0; ti<4; ti++){
            const int n0 = (half*4 + ti)*8;
            const int lrow = grp*16 + rquad;
            const int rbase = blockIdx.x*64 + lrow;
            float2 v0; v0.x = hp[ti][0]; v0.y = hp[ti][1];
            float2 v1; v1.x = hp[ti][2]; v1.y = hp[ti][3];
            *(float2*)(g_hidden + (size_t)rbase*64     + n0 + 2*c) = v0;
            *(float2*)(g_hidden + (size_t)(rbase+8)*64 + n0 + 2*c) = v1;
            sh[lrow*65     + n0 + 2*c] = hp[ti][0];
            sh[lrow*65     + n0 + 2*c + 1] = hp[ti][1];
            sh[(lrow+8)*65 + n0 + 2*c] = hp[ti][2];
            sh[(lrow+8)*65 + n0 + 2*c + 1] = hp[ti][3];
        }
    }
    float* sT = (float*)(sm + WI1HI);  // trW transposed [k*64+j]
    float* sA = (float*)(sm + W0HI);   // a1(64), a2(64), trb(64)
    for (int idx=tid; idx<4096; idx+=512){
        int j = idx>>6, k = idx&63;
        sT[k*64+j] = trW[idx];
    }
    if (tid < 128) sA[tid] = av[tid];
    else if (tid < 192) sA[tid] = trb[tid-128];
    __syncthreads();
    {
        const int r = tid>>3, j0 = (tid&7)*8;
        float acc[8];
        #pragma unroll
        for (int jj=0;jj<8;jj++) acc[jj] = sA[128 + j0 + jj];
        #pragma unroll 8
        for (int k=0;k<64;k++){
            float hv = sh[r*65 + k];
            #pragma unroll
            for (int jj=0;jj<8;jj++) acc[jj] += hv * sT[k*64 + j0 + jj];
        }
        float p1 = 0.f, p2 = 0.f;
        #pragma unroll
        for (int jj=0;jj<8;jj++){
            p1 += acc[jj]*sA[j0+jj];
            p2 += acc[jj]*sA[64+j0+jj];
        }
        #pragma unroll
        for (int off=4; off; off>>=1){
            p1 += __shfl_down_sync(0xffffffffu, p1, off, 8);
            p2 += __shfl_down_sync(0xffffffffu, p2, off, 8);
        }
        if ((tid&7)==0){
            int n = blockIdx.x*64 + r;
            g_s1[n] = p1; g_s2[n] = p2;
            unsigned u = f2u(p1);
            g_keys32[n] = ((u >> 13) << 13) | (unsigned)n;
        }
    }
}

__global__ __launch_bounds__(1024) void sortA_kernel(){
    __shared__ unsigned sk[1024];
    int b = blockIdx.x, tid = threadIdx.x;
    sk[tid] = g_keys32[b*1024 + tid];
    __syncthreads();
    for (int k=2; k<=1024; k<<=1){
        for (int j=k>>1; j>0; j>>=1){
            int ixj = tid^j;
            if (ixj > tid){
                unsigned va = sk[tid], vb = sk[ixj];
                bool up = ((tid & k) == 0);
                if ((va > vb) == up){ sk[tid]=vb; sk[ixj]=va; }
            }
            __syncthreads();
        }
    }
    g_schunk[b*1024 + tid] = sk[tid];
}

// rank-merge + exp (fused)
__global__ __launch_bounds__(256) void sortB_kernel(){
    int i = blockIdx.x*256 + threadIdx.x;
    int b = i >> 10;
    unsigned key = g_schunk[i];
    int rank = i & 1023;
    #pragma unroll 1
    for (int ob=0; ob<8; ob++){
        if (ob == b) continue;
        const unsigned* ch = g_schunk + ob*1024;
        int lo = 0, hi = 1024;
        while (lo < hi){ int mid = (lo+hi)>>1; if (ch[mid] < key) lo = mid+1; else hi = mid; }
        rank += lo;
    }
    int idx = (int)(key & 8191u);
    float s1v = g_s1[idx];
    g_perm[rank]  = idx;
    g_s1s[rank]   = s1v;
    g_ksort[rank] = key;
    g_e1[rank]  = exp((double)s1v);
    g_e01[rank] = exp(0.01*(double)s1v);
}

__global__ __launch_bounds__(1024) void scan_kernel(){
    __shared__ double wsum[32];
    __shared__ double sbase[33];
    int c = blockIdx.x, tid = threadIdx.x;
    int lane = tid & 31, wid = tid >> 5;
    int nscans = (c == 128) ? 2 : 1;
    for (int s=0; s<nscans; s++){
        double local[8], ts = 0.0;
        #pragma unroll
        for (int e=0; e<8; e++){
            int r = tid*8 + e;
            double w;
            if (c < 64)       w = g_e1[r]  * (double)g_hidden[g_perm[r]*HH + c];
            else if (c < 128) w = g_e01[r] * (double)g_hidden[g_perm[r]*HH + (c-64)];
            else              w = (s == 0) ? g_e1[r] : g_e01[r];
            local[e] = w; ts += w;
        }
        double incl = ts;
        #pragma unroll
        for (int off=1; off<32; off<<=1){
            double v = __shfl_up_sync(0xffffffffu, incl, off);
            if (lane >= off) incl += v;
        }
        if (lane == 31) wsum[wid] = incl;
        __syncthreads();
        if (wid == 0){
            double iv = wsum[lane];
            #pragma unroll
            for (int off=1; off<32; off<<=1){
                double u = __shfl_up_sync(0xffffffffu, iv, off);
                if (lane >= off) iv += u;
            }
            sbase[lane+1] = iv;
            if (lane == 0) sbase[0] = 0.0;
        }
        __syncthreads();
        double run = sbase[wid] + (incl - ts);
        #pragma unroll
        for (int e=0; e<8; e++){
            int r = tid*8 + e;
            if (c < 64)       g_prefP[r*HH + c]      = run;
            else if (c < 128) g_prefQ[r*HH + (c-64)] = run;
            else              g_prefE[r*2 + s]        = run;
            run += local[e];
        }
        if (tid == 0){
            double tot = sbase[32];
            if (c < 64)       g_prefP[NN*HH + c]      = tot;
            else if (c < 128) g_prefQ[NN*HH + (c-64)] = tot;
            else              g_prefE[NN*2 + s]        = tot;
        }
        __syncthreads();
    }
}

__global__ __launch_bounds__(256) void final_kernel(
    const float* __restrict__ fcW, const float* __restrict__ fcb,
    const float* __restrict__ outW, const float* __restrict__ outb,
    float* __restrict__ out)
{
    __shared__ float sFcT[HH*HH];
    __shared__ float sOw[HH], sFb[HH];
    __shared__ float sH[8][HH];
    int tid = threadIdx.x;
    for (int idx=tid; idx<HH*HH; idx+=256){ int o=idx>>6, k=idx&63; sFcT[k*HH+o]=fcW[idx]; }
    if (tid < HH){ sOw[tid]=outW[tid]; sFb[tid]=fcb[tid]; }
    int w = tid>>5, lane = tid&31;
    int i = blockIdx.x*8 + w;
    float s2 = g_s2[i];
    unsigned thrkey = (f2u(-s2) >> 13) << 13;
    int lo = 0, hi = NN;
    while (lo < hi){ int mid = (lo+hi)>>1; if (g_ksort[mid] < thrkey) lo = mid+1; else hi = mid; }
    int m = lo;
    double e2p = exp((double)s2), e2n = exp(0.01*(double)s2);
    double den = e2p*(g_prefE[NN*2+0] - g_prefE[m*2+0]) + e2n*g_prefE[m*2+1];
    __syncthreads();
    #pragma unroll
    for (int q=0; q<2; q++){
        int d = lane + q*32;
        double Pt = g_prefP[NN*HH + d];
        double num = e2p*(Pt - g_prefP[m*HH + d]) + e2n*g_prefQ[m*HH + d];
        sH[w][d] = (float)(num/den) + g_hidden[i*HH + d];
    }
    __syncwarp();
    float partial = 0.f;
    #pragma unroll
    for (int q=0; q<2; q++){
        int o = lane + q*32;
        float acc = sFb[o];
        #pragma unroll 8
        for (int k=0; k<HH; k++) acc += sFcT[k*HH+o]*sH[w][k];
        acc = (acc >= 0.f) ? acc : 0.01f*acc;
        partial += acc*sOw[o];
    }
    #pragma unroll
    for (int off=16; off; off>>=1) partial += __shfl_down_sync(0xffffffffu, partial, off);
    if (lane == 0) out[i] = partial + outb[0];
}

extern "C" void kernel_launch(void* const* d_in, const int* in_sizes, int n_in,
                              void* d_out, int out_size)
{
    const float* x    = (const float*)d_in[0];
    const float* Wih0 = (const float*)d_in[1];
    const float* Whh0 = (const float*)d_in[2];
    const float* bih0 = (const float*)d_in[3];
    const float* bhh0 = (const float*)d_in[4];
    const float* Wih1 = (const float*)d_in[5];
    const float* Whh1 = (const float*)d_in[6];
    const float* bih1 = (const float*)d_in[7];
    const float* bhh1 = (const float*)d_in[8];
    const float* trW  = (const float*)d_in[9];
    const float* trb  = (const float*)d_in[10];
    const float* a    = (const float*)d_in[11];
    const float* fcW  = (const float*)d_in[12];
    const float* fcb  = (const float*)d_in[13];
    const float* outW = (const float*)d_in[14];
    const float* outb = (const float*)d_in[15];

    cudaFuncSetAttribute(gru_kernel, cudaFuncAttributeMaxDynamicSharedMemorySize, SMEM_GRU);

    transpose_kernel<<<NN/32, 256>>>(x);
    gru_kernel<<<128, 512, SMEM_GRU>>>(Wih0, Whh0, bih0, bhh0, Wih1, Whh1, bih1, bhh1, trW, trb, a);
    sortA_kernel<<<8, 1024>>>();
    sortB_kernel<<<NN/256, 256>>>();
    scan_kernel<<<129, 1024>>>();
    final_kernel<<<NN/8, 256>>>(fcW, fcb, outW, outb, (float*)d_out);
}